// round 12
// baseline (speedup 1.0000x reference)
#include <cuda_runtime.h>
#include <cuda_bf16.h>
#include <math.h>
#include <stdint.h>

// Problem constants
#define BB 4
#define NN 2048
#define DD 512
#define HH 8
#define HDIM 64
#define MROWS (BB*NN)          // 8192

// ---------------- scratch (static device globals; no runtime allocation) ---
__device__ float g_qkv[MROWS*1536];
__device__ float g_hcat[MROWS*1024];
__device__ float g_h1[MROWS*1024];
__device__ float g_wr[2621440];           // tf32-rounded [N][K] weights (FFN1/FFN2)
__device__ uint32_t g_qb[MROWS*256];      // bf16x2 Q [bh][n][d/2], pre-scaled
__device__ uint32_t g_kb[MROWS*256];      // bf16x2 K [bh][n][d/2]
__device__ uint32_t g_vtb[MROWS*256];     // bf16x2 V^T [bh][d][n/2]
__device__ uint32_t g_xb[MROWS*256];      // bf16x2 x [m][k/2]
__device__ uint32_t g_ab[MROWS*256];      // bf16x2 attn out [m][k/2]
__device__ uint32_t g_wqkvb[1536*256];    // bf16x2 wqkv^T [1536][256]
__device__ uint32_t g_woutb[512*256];     // bf16x2 out_w^T [512][256]

#define WOFF_FFN1 1048576                  // [1024][1024]
#define WOFF_FFN2 2097152                  // [512][1024]

// ------------------------------------------------------------ utils --------
__device__ __forceinline__ uint32_t f2tf32(float x) {
    uint32_t u;
    asm volatile("cvt.rna.tf32.f32 %0, %1;" : "=r"(u) : "f"(x));
    return u;
}
__device__ __forceinline__ float roundtf(float x) {
    return __uint_as_float(f2tf32(x));
}
__device__ __forceinline__ uint32_t pack_bf16(float a, float b) {
    uint32_t r;
    asm("cvt.rn.bf16x2.f32 %0, %1, %2;" : "=r"(r) : "f"(b), "f"(a));
    return r;
}

__device__ __forceinline__ void mma_tf32(float c[4],
                                         const uint32_t a[4],
                                         const uint32_t b[2]) {
    asm volatile(
        "mma.sync.aligned.m16n8k8.row.col.f32.tf32.tf32.f32 "
        "{%0,%1,%2,%3}, {%4,%5,%6,%7}, {%8,%9}, {%0,%1,%2,%3};\n"
        : "+f"(c[0]), "+f"(c[1]), "+f"(c[2]), "+f"(c[3])
        : "r"(a[0]), "r"(a[1]), "r"(a[2]), "r"(a[3]),
          "r"(b[0]), "r"(b[1]));
}

__device__ __forceinline__ void mma_bf16(float c[4],
                                         const uint32_t a[4],
                                         uint32_t b0, uint32_t b1) {
    asm volatile(
        "mma.sync.aligned.m16n8k16.row.col.f32.bf16.bf16.f32 "
        "{%0,%1,%2,%3}, {%4,%5,%6,%7}, {%8,%9}, {%0,%1,%2,%3};\n"
        : "+f"(c[0]), "+f"(c[1]), "+f"(c[2]), "+f"(c[3])
        : "r"(a[0]), "r"(a[1]), "r"(a[2]), "r"(a[3]),
          "r"(b0), "r"(b1));
}

__device__ __forceinline__ void cp_async16(uint32_t saddr, const void* gptr) {
    asm volatile("cp.async.cg.shared.global [%0], [%1], 16;\n"
                 :: "r"(saddr), "l"(gptr));
}
#define CP_COMMIT() asm volatile("cp.async.commit_group;\n" ::: "memory")
#define CP_WAIT1()  asm volatile("cp.async.wait_group 1;\n" ::: "memory")
#define CP_WAIT2()  asm volatile("cp.async.wait_group 2;\n" ::: "memory")

// ---------------- round x (hcat left) + pack x to bf16 ---------------------
__global__ __launch_bounds__(256) void round_x(const float* __restrict__ x)
{
    int idx = blockIdx.x * blockDim.x + threadIdx.x;  // float4 index
    if (idx >= MROWS*DD/4) return;
    float4 v = ((const float4*)x)[idx];
    // bf16 pack for QKV GEMM A
    uint2 p;
    p.x = pack_bf16(v.x, v.y);
    p.y = pack_bf16(v.z, v.w);
    ((uint2*)g_xb)[idx] = p;
    // tf32 round for hcat left half (feeds FFN1)
    v.x = roundtf(v.x); v.y = roundtf(v.y);
    v.z = roundtf(v.z); v.w = roundtf(v.w);
    int m = idx >> 7, j = idx & 127;
    ((float4*)g_hcat)[m * 256 + j] = v;
}

// -------------- transpose + tf32-round weights (FFN1/FFN2) -----------------
// src [K][N] -> dst [N][K].  grid (N/32, K/32), block (32,8).
__global__ __launch_bounds__(256) void transpose_round(
    const float* __restrict__ src, float* __restrict__ dst, int K, int N)
{
    __shared__ float t[32][33];
    int k0 = blockIdx.y * 32, n0 = blockIdx.x * 32;
    int x = threadIdx.x, y = threadIdx.y;
    #pragma unroll
    for (int j = 0; j < 4; j++)
        t[y + 8*j][x] = src[(size_t)(k0 + y + 8*j) * N + n0 + x];
    __syncthreads();
    #pragma unroll
    for (int j = 0; j < 4; j++)
        dst[(size_t)(n0 + y + 8*j) * K + k0 + x] = roundtf(t[x][y + 8*j]);
}

// -------------- transpose + bf16-pack weights (QKV / out-proj) -------------
// src [K][N] f32 -> dst [N][K/2] bf16x2.  grid (N/32, K/64), block (32,8).
__global__ __launch_bounds__(256) void transpose_pack_bf16(
    const float* __restrict__ src, uint32_t* __restrict__ dst, int K, int N)
{
    __shared__ float t[64][33];
    int k0 = blockIdx.y * 64, n0 = blockIdx.x * 32;
    int x = threadIdx.x, y = threadIdx.y;
    #pragma unroll
    for (int j = 0; j < 8; j++)
        t[y + 8*j][x] = src[(size_t)(k0 + y + 8*j) * N + n0 + x];
    __syncthreads();
    #pragma unroll
    for (int j = 0; j < 4; j++) {
        int n = y + 8*j;
        dst[(size_t)(n0 + n) * (K/2) + (k0 >> 1) + x] =
            pack_bf16(t[2*x][n], t[2*x+1][n]);
    }
}

// ---------------- 4-stage pipelined tf32 GEMM, 64x64 warp tiles ------------
// A [M][K] pad 20; Bt [N][K] pad 20 (no permutation).  All frags 2xLDS.32,
// banks (20g+tg) conflict-free.
#define GBM 128
#define GBN 128
#define GBK 16
#define APADW 20
#define BPADW 20
#define BOFF_W (GBM*APADW)                    // 2560 words
#define STAGE_W (GBM*APADW + GBN*BPADW)       // 5120 words
#define STAGE_B (STAGE_W*4)                   // 20480 bytes
#define GEMM_SMEM (4*STAGE_B)                 // 81920 bytes

__global__ __launch_bounds__(128) void gemm_tf32(
    const float* __restrict__ A, int lda,
    const float* __restrict__ Bt, int ldb,
    float* __restrict__ C, int ldc,
    const float* __restrict__ bias,
    const float* __restrict__ res, int ldres,
    int K, int roundC)
{
    extern __shared__ uint32_t gsm[];
    const uint32_t sbase = (uint32_t)__cvta_generic_to_shared(gsm);

    const int tid  = threadIdx.x;
    const int brow = blockIdx.y * GBM;
    const int bcol = blockIdx.x * GBN;
    const int w    = tid >> 5;
    const int lane = tid & 31;
    const int g    = lane >> 2;
    const int tg   = lane & 3;
    const int wm   = (w & 1) * 64;
    const int wn   = (w >> 1) * 64;

    int arow[4], achk[4];
    uint32_t offA[4], offB[4];
    #pragma unroll
    for (int i = 0; i < 4; i++) {
        int idx = tid + i * 128;
        arow[i] = idx >> 2;
        achk[i] = (idx & 3) * 4;
        offA[i] = (uint32_t)(arow[i] * APADW + achk[i]) * 4;
        offB[i] = (uint32_t)(BOFF_W + arow[i] * BPADW + achk[i]) * 4;
    }

    float acc[4][8][4];
    #pragma unroll
    for (int mi = 0; mi < 4; mi++)
        #pragma unroll
        for (int ni = 0; ni < 8; ni++)
            #pragma unroll
            for (int q = 0; q < 4; q++) acc[mi][ni][q] = 0.f;

    const int nk = K / GBK;

    #pragma unroll
    for (int s = 0; s < 3; s++) {
        const uint32_t sb = sbase + s * STAGE_B;
        const int k0 = s * GBK;
        #pragma unroll
        for (int i = 0; i < 4; i++) {
            cp_async16(sb + offA[i], &A[(size_t)(brow + arow[i]) * lda + k0 + achk[i]]);
            cp_async16(sb + offB[i], &Bt[(size_t)(bcol + arow[i]) * ldb + k0 + achk[i]]);
        }
        CP_COMMIT();
    }

    for (int kt = 0; kt < nk; kt++) {
        CP_WAIT2();
        __syncthreads();
        if (kt + 3 < nk) {
            const uint32_t sb = sbase + ((kt + 3) & 3) * STAGE_B;
            const int k0 = (kt + 3) * GBK;
            #pragma unroll
            for (int i = 0; i < 4; i++) {
                cp_async16(sb + offA[i], &A[(size_t)(brow + arow[i]) * lda + k0 + achk[i]]);
                cp_async16(sb + offB[i], &Bt[(size_t)(bcol + arow[i]) * ldb + k0 + achk[i]]);
            }
        }
        CP_COMMIT();

        const uint32_t* Asb = gsm + (kt & 3) * STAGE_W;
        const uint32_t* Bsb = Asb + BOFF_W;

        #pragma unroll
        for (int ks = 0; ks < 2; ks++) {
            const int kk = ks * 8;
            uint32_t af[4][4], bf[8][2];
            #pragma unroll
            for (int mi = 0; mi < 4; mi++) {
                int r = wm + mi * 16 + g;
                af[mi][0] = Asb[r * APADW + kk + tg];
                af[mi][1] = Asb[(r + 8) * APADW + kk + tg];
                af[mi][2] = Asb[r * APADW + kk + tg + 4];
                af[mi][3] = Asb[(r + 8) * APADW + kk + tg + 4];
            }
            #pragma unroll
            for (int ni = 0; ni < 8; ni++) {
                int c = wn + ni * 8 + g;
                bf[ni][0] = Bsb[c * BPADW + kk + tg];
                bf[ni][1] = Bsb[c * BPADW + kk + tg + 4];
            }
            #pragma unroll
            for (int mi = 0; mi < 4; mi++)
                #pragma unroll
                for (int ni = 0; ni < 8; ni++)
                    mma_tf32(acc[mi][ni], af[mi], bf[ni]);
        }
    }

    #pragma unroll
    for (int mi = 0; mi < 4; mi++) {
        int r0 = brow + wm + mi * 16 + g;
        int r1 = r0 + 8;
        #pragma unroll
        for (int ni = 0; ni < 8; ni++) {
            int cc = bcol + wn + ni * 8 + tg * 2;
            float2 b2 = *(const float2*)&bias[cc];
            float v0 = acc[mi][ni][0] + b2.x;
            float v1 = acc[mi][ni][1] + b2.y;
            float v2 = acc[mi][ni][2] + b2.x;
            float v3 = acc[mi][ni][3] + b2.y;
            if (res) {
                float2 ra = *(const float2*)&res[(size_t)r0 * ldres + cc];
                float2 rb = *(const float2*)&res[(size_t)r1 * ldres + cc];
                v0 += ra.x; v1 += ra.y; v2 += rb.x; v3 += rb.y;
            }
            if (roundC) {
                v0 = roundtf(v0); v1 = roundtf(v1);
                v2 = roundtf(v2); v3 = roundtf(v3);
            }
            *(float2*)&C[(size_t)r0 * ldc + cc] = make_float2(v0, v1);
            *(float2*)&C[(size_t)r1 * ldc + cc] = make_float2(v2, v3);
        }
    }
}

// ---------------- 4-stage pipelined bf16 GEMM (QKV, out-proj) --------------
// A [M][Kw] bf16x2 words, Bt [N][Kw] bf16x2 words, pad 20.  K-chunk = 16
// words (32 dims = 2 k16 steps).
#define BSTAGE_W (2 * 128 * 20)              // 5120 words
#define BSTAGE_B (BSTAGE_W * 4)
#define BGEMM_SMEM (4 * BSTAGE_B)            // 81920 bytes

__global__ __launch_bounds__(128) void gemm_bf16(
    const uint32_t* __restrict__ A, int ldaw,
    const uint32_t* __restrict__ Bt, int ldbw,
    float* __restrict__ C, int ldc,
    const float* __restrict__ bias,
    int Kw, int roundC)
{
    extern __shared__ uint32_t gsm[];
    const uint32_t sbase = (uint32_t)__cvta_generic_to_shared(gsm);

    const int tid  = threadIdx.x;
    const int brow = blockIdx.y * 128;
    const int bcol = blockIdx.x * 128;
    const int w    = tid >> 5;
    const int lane = tid & 31;
    const int g    = lane >> 2;
    const int tg   = lane & 3;
    const int wm   = (w & 1) * 64;
    const int wn   = (w >> 1) * 64;

    int arow[4], achk[4];
    uint32_t offA[4], offB[4];
    #pragma unroll
    for (int i = 0; i < 4; i++) {
        int idx = tid + i * 128;
        arow[i] = idx >> 2;
        achk[i] = (idx & 3) * 4;
        offA[i] = (uint32_t)(arow[i] * 20 + achk[i]) * 4;
        offB[i] = (uint32_t)(128 * 20 + arow[i] * 20 + achk[i]) * 4;
    }

    float acc[4][8][4];
    #pragma unroll
    for (int mi = 0; mi < 4; mi++)
        #pragma unroll
        for (int ni = 0; ni < 8; ni++)
            #pragma unroll
            for (int q = 0; q < 4; q++) acc[mi][ni][q] = 0.f;

    const int nk = Kw / 16;

    #pragma unroll
    for (int s = 0; s < 3; s++) {
        const uint32_t sb = sbase + s * BSTAGE_B;
        const int k0 = s * 16;
        #pragma unroll
        for (int i = 0; i < 4; i++) {
            cp_async16(sb + offA[i], &A[(size_t)(brow + arow[i]) * ldaw + k0 + achk[i]]);
            cp_async16(sb + offB[i], &Bt[(size_t)(bcol + arow[i]) * ldbw + k0 + achk[i]]);
        }
        CP_COMMIT();
    }

    for (int kt = 0; kt < nk; kt++) {
        CP_WAIT2();
        __syncthreads();
        if (kt + 3 < nk) {
            const uint32_t sb = sbase + ((kt + 3) & 3) * BSTAGE_B;
            const int k0 = (kt + 3) * 16;
            #pragma unroll
            for (int i = 0; i < 4; i++) {
                cp_async16(sb + offA[i], &A[(size_t)(brow + arow[i]) * ldaw + k0 + achk[i]]);
                cp_async16(sb + offB[i], &Bt[(size_t)(bcol + arow[i]) * ldbw + k0 + achk[i]]);
            }
        }
        CP_COMMIT();

        const uint32_t* Asb = gsm + (kt & 3) * BSTAGE_W;
        const uint32_t* Bsb = Asb + 128 * 20;

        #pragma unroll
        for (int ks = 0; ks < 2; ks++) {
            const int kk = ks * 8;
            uint32_t af[4][4], bf[8][2];
            #pragma unroll
            for (int mi = 0; mi < 4; mi++) {
                int r = wm + mi * 16 + g;
                af[mi][0] = Asb[r * 20 + kk + tg];
                af[mi][1] = Asb[(r + 8) * 20 + kk + tg];
                af[mi][2] = Asb[r * 20 + kk + tg + 4];
                af[mi][3] = Asb[(r + 8) * 20 + kk + tg + 4];
            }
            #pragma unroll
            for (int ni = 0; ni < 8; ni++) {
                int c = wn + ni * 8 + g;
                bf[ni][0] = Bsb[c * 20 + kk + tg];
                bf[ni][1] = Bsb[c * 20 + kk + tg + 4];
            }
            #pragma unroll
            for (int mi = 0; mi < 4; mi++)
                #pragma unroll
                for (int ni = 0; ni < 8; ni++)
                    mma_bf16(acc[mi][ni], af[mi], bf[ni][0], bf[ni][1]);
        }
    }

    #pragma unroll
    for (int mi = 0; mi < 4; mi++) {
        int r0 = brow + wm + mi * 16 + g;
        int r1 = r0 + 8;
        #pragma unroll
        for (int ni = 0; ni < 8; ni++) {
            int cc = bcol + wn + ni * 8 + tg * 2;
            float2 b2 = *(const float2*)&bias[cc];
            float v0 = acc[mi][ni][0] + b2.x;
            float v1 = acc[mi][ni][1] + b2.y;
            float v2 = acc[mi][ni][2] + b2.x;
            float v3 = acc[mi][ni][3] + b2.y;
            if (roundC) {
                v0 = roundtf(v0); v1 = roundtf(v1);
                v2 = roundtf(v2); v3 = roundtf(v3);
            }
            *(float2*)&C[(size_t)r0 * ldc + cc] = make_float2(v0, v1);
            *(float2*)&C[(size_t)r1 * ldc + cc] = make_float2(v2, v3);
        }
    }
}

// ------------------------------------------------------------ RoPE split ---
__global__ void rope_kernel(const float* __restrict__ freqs)
{
    int idx = blockIdx.x * blockDim.x + threadIdx.x;
    if (idx >= BB * NN * HH * 32) return;
    int i = idx & 31;
    int h = (idx >> 5) & 7;
    int n = (idx >> 8) & 2047;
    int b = idx >> 19;

    float f = freqs[(b * NN + n) * 32 + i];
    float c = cosf(f), s = sinf(f);

    int base = (b * NN + n) * 1536 + h * 64;
    int ow   = ((b * HH + h) * NN + n) * 32 + i;

    float q1 = g_qkv[base + 2*i], q2 = g_qkv[base + 2*i + 1];
    g_qb[ow] = pack_bf16((q1 * c - q2 * s) * 0.125f,
                         (q1 * s + q2 * c) * 0.125f);

    float k1 = g_qkv[base + 512 + 2*i], k2 = g_qkv[base + 512 + 2*i + 1];
    g_kb[ow] = pack_bf16(k1 * c - k2 * s, k1 * s + k2 * c);
}

// ----------------------------------------------- V transpose to bf16x2 -----
__global__ __launch_bounds__(128) void vtrans_kernel()
{
    __shared__ float ts[64 * 65];
    const int bh = blockIdx.x;
    const int b = bh >> 3, h = bh & 7;
    const int n0 = blockIdx.y * 64;
    const int tid = threadIdx.x;

    {
        const int r = tid >> 1, cb = (tid & 1) * 32;
        const float* src = g_qkv + (size_t)(b * NN + n0 + r) * 1536 + 1024 + h * 64 + cb;
        #pragma unroll
        for (int c = 0; c < 8; c++) {
            float4 v = *(const float4*)&src[c * 4];
            float* d = &ts[r * 65 + cb + c * 4];
            d[0] = v.x; d[1] = v.y; d[2] = v.z; d[3] = v.w;
        }
    }
    __syncthreads();

    const int wp = tid >> 5, p = tid & 31;
    #pragma unroll
    for (int it = 0; it < 16; it++) {
        const int d = wp + it * 4;
        uint32_t word = pack_bf16(ts[(2 * p) * 65 + d], ts[(2 * p + 1) * 65 + d]);
        g_vtb[(size_t)(bh * 64 + d) * 1024 + (n0 >> 1) + p] = word;
    }
}

// ---------------------------- bf16 flash attention, cp.async 3-stage ring --
#define VSW 36
#define STG_W (64 * VSW * 2)
#define VOFF_B (64 * VSW * 4)
#define ATT_SMEM (3 * STG_W * 4)       // 55296 B

__global__ __launch_bounds__(256, 2) void attn_bf16()
{
    extern __shared__ uint32_t sm[];
    const uint32_t sbase = (uint32_t)__cvta_generic_to_shared(sm);

    const int bh = blockIdx.y;
    const int q0 = blockIdx.x * 128;
    const uint32_t* __restrict__ Qw = g_qb + (size_t)bh * NN * 32;
    const uint32_t* __restrict__ Kw = g_kb + (size_t)bh * NN * 32;
    const uint32_t* __restrict__ Vw = g_vtb + (size_t)bh * 64 * 1024;

    const int tid  = threadIdx.x;
    const int w    = tid >> 5;
    const int lane = tid & 31;
    const int g    = lane >> 2;
    const int tg   = lane & 3;
    const int w16  = w * 16;

    uint32_t qa[4][4];
    {
        const int r0 = q0 + w16 + g, r1 = r0 + 8;
        #pragma unroll
        for (int ks = 0; ks < 4; ks++) {
            qa[ks][0] = Qw[r0 * 32 + ks * 8 + tg];
            qa[ks][1] = Qw[r1 * 32 + ks * 8 + tg];
            qa[ks][2] = Qw[r0 * 32 + ks * 8 + tg + 4];
            qa[ks][3] = Qw[r1 * 32 + ks * 8 + tg + 4];
        }
    }

    const int row0 = tid >> 3;
    const int cc   = (tid & 7) * 4;
    const uint32_t dst0 = (uint32_t)(row0 * VSW + cc) * 4;
    const uint32_t dst1 = (uint32_t)((row0 + 32) * VSW + cc) * 4;

    float m0 = -1e30f, m1 = -1e30f, l0 = 0.f, l1 = 0.f;
    float oacc[8][4];
    #pragma unroll
    for (int nt = 0; nt < 8; nt++)
        #pragma unroll
        for (int q = 0; q < 4; q++) oacc[nt][q] = 0.f;

    #pragma unroll
    for (int s = 0; s < 2; s++) {
        const uint32_t sb = sbase + s * STG_W * 4;
        const int k0 = s * 64;
        cp_async16(sb + dst0, Kw + (k0 + row0) * 32 + cc);
        cp_async16(sb + dst1, Kw + (k0 + row0 + 32) * 32 + cc);
        cp_async16(sb + VOFF_B + dst0, Vw + row0 * 1024 + (k0 >> 1) + cc);
        cp_async16(sb + VOFF_B + dst1, Vw + (row0 + 32) * 1024 + (k0 >> 1) + cc);
        CP_COMMIT();
    }

    int stage = 0;
    for (int kt = 0; kt < 32; kt++) {
        CP_WAIT1();
        __syncthreads();
        if (kt + 2 < 32) {
            const int s2 = (stage + 2 >= 3) ? stage - 1 : stage + 2;
            const uint32_t sb = sbase + s2 * STG_W * 4;
            const int k0 = (kt + 2) * 64;
            cp_async16(sb + dst0, Kw + (k0 + row0) * 32 + cc);
            cp_async16(sb + dst1, Kw + (k0 + row0 + 32) * 32 + cc);
            cp_async16(sb + VOFF_B + dst0, Vw + row0 * 1024 + (k0 >> 1) + cc);
            cp_async16(sb + VOFF_B + dst1, Vw + (row0 + 32) * 1024 + (k0 >> 1) + cc);
        }
        CP_COMMIT();

        const uint32_t* Ks  = sm + stage * STG_W;
        const uint32_t* Vst = Ks + 64 * VSW;
        stage = (stage + 1 == 3) ? 0 : stage + 1;

        float sacc[8][4];
        #pragma unroll
        for (int nt = 0; nt < 8; nt++)
            #pragma unroll
            for (int q = 0; q < 4; q++) sacc[nt][q] = 0.f;

        #pragma unroll
        for (int ks = 0; ks < 4; ks++) {
            const int wb = ks * 8;
            #pragma unroll
            for (int nt = 0; nt < 8; nt++) {
                const uint32_t* row = &Ks[(nt * 8 + g) * VSW];
                mma_bf16(sacc[nt], qa[ks], row[wb + tg], row[wb + 4 + tg]);
            }
        }

        float mt0 = -1e30f, mt1 = -1e30f;
        #pragma unroll
        for (int nt = 0; nt < 8; nt++) {
            mt0 = fmaxf(mt0, fmaxf(sacc[nt][0], sacc[nt][1]));
            mt1 = fmaxf(mt1, fmaxf(sacc[nt][2], sacc[nt][3]));
        }
        mt0 = fmaxf(mt0, __shfl_xor_sync(0xffffffffu, mt0, 1));
        mt0 = fmaxf(mt0, __shfl_xor_sync(0xffffffffu, mt0, 2));
        mt1 = fmaxf(mt1, __shfl_xor_sync(0xffffffffu, mt1, 1));
        mt1 = fmaxf(mt1, __shfl_xor_sync(0xffffffffu, mt1, 2));
        float mn0 = fmaxf(m0, mt0), mn1 = fmaxf(m1, mt1);

        float rs0 = 0.f, rs1 = 0.f;
        #pragma unroll
        for (int nt = 0; nt < 8; nt++) {
            sacc[nt][0] = __expf(sacc[nt][0] - mn0);
            sacc[nt][1] = __expf(sacc[nt][1] - mn0);
            sacc[nt][2] = __expf(sacc[nt][2] - mn1);
            sacc[nt][3] = __expf(sacc[nt][3] - mn1);
            rs0 += sacc[nt][0] + sacc[nt][1];
            rs1 += sacc[nt][2] + sacc[nt][3];
        }
        rs0 += __shfl_xor_sync(0xffffffffu, rs0, 1);
        rs0 += __shfl_xor_sync(0xffffffffu, rs0, 2);
        rs1 += __shfl_xor_sync(0xffffffffu, rs1, 1);
        rs1 += __shfl_xor_sync(0xffffffffu, rs1, 2);

        float c0 = __expf(m0 - mn0), c1 = __expf(m1 - mn1);
        l0 = l0 * c0 + rs0;  l1 = l1 * c1 + rs1;
        m0 = mn0;            m1 = mn1;
        #pragma unroll
        for (int nt = 0; nt < 8; nt++) {
            oacc[nt][0] *= c0; oacc[nt][1] *= c0;
            oacc[nt][2] *= c1; oacc[nt][3] *= c1;
        }

        uint32_t pa[8][2];
        #pragma unroll
        for (int nt = 0; nt < 8; nt++) {
            pa[nt][0] = pack_bf16(sacc[nt][0], sacc[nt][1]);
            pa[nt][1] = pack_bf16(sacc[nt][2], sacc[nt][3]);
        }

        #pragma unroll
        for (int ks = 0; ks < 4; ks++) {
            const int wb = ks * 8;
            uint32_t a[4] = { pa[2*ks][0], pa[2*ks][1],
                              pa[2*ks+1][0], pa[2*ks+1][1] };
            #pragma unroll
            for (int nt = 0; nt < 8; nt++) {
                const uint32_t* row = &Vst[(nt * 8 + g) * VSW];
                mma_bf16(oacc[nt], a, row[wb + tg], row[wb + 4 + tg]);
            }
        }
    }

    // ---- write out packed bf16 [m][d/2] (feeds out-proj bf16 GEMM A) ----
    const int b = bh >> 3, h = bh & 7;
    const float inv0 = 1.f / l0, inv1 = 1.f / l1;
    const int r0 = q0 + w16 + g, r1 = r0 + 8;
    #pragma unroll
    for (int nt = 0; nt < 8; nt++) {
        int wd = h * 32 + nt * 4 + tg;   // word index of dims (d, d+1)
        g_ab[(size_t)(b * NN + r0) * 256 + wd] =
            pack_bf16(oacc[nt][0] * inv0, oacc[nt][1] * inv0);
        g_ab[(size_t)(b * NN + r1) * 256 + wd] =
            pack_bf16(oacc[nt][2] * inv1, oacc[nt][3] * inv1);
    }
}

// ------------------------------------------------------- LayerNorm + GELU --
__global__ __launch_bounds__(256) void ln_gelu_kernel(
    const float* __restrict__ gamma, const float* __restrict__ beta)
{
    const int r = blockIdx.x;
    const int t = threadIdx.x;
    float4 v = *(const float4*)&g_h1[(size_t)r * 1024 + t * 4];

    float sum = v.x + v.y + v.z + v.w;
    float sq  = v.x*v.x + v.y*v.y + v.z*v.z + v.w*v.w;
    #pragma unroll
    for (int off = 16; off >= 1; off >>= 1) {
        sum += __shfl_xor_sync(0xffffffffu, sum, off);
        sq  += __shfl_xor_sync(0xffffffffu, sq, off);
    }
    __shared__ float ssum[8], ssq[8];
    if ((t & 31) == 0) { ssum[t >> 5] = sum; ssq[t >> 5] = sq; }
    __syncthreads();
    float tot = 0.f, totq = 0.f;
    #pragma unroll
    for (int w = 0; w < 8; w++) { tot += ssum[w]; totq += ssq[w]; }

    float mean = tot * (1.f / 1024.f);
    float var  = totq * (1.f / 1024.f) - mean * mean;
    float inv  = rsqrtf(var + 1e-5f);

    float4 g4 = *(const float4*)&gamma[t * 4];
    float4 b4 = *(const float4*)&beta[t * 4];
    float y; float4 o;
    y = (v.x - mean) * inv * g4.x + b4.x; o.x = roundtf(0.5f * y * (1.f + erff(y * 0.70710678f)));
    y = (v.y - mean) * inv * g4.y + b4.y; o.y = roundtf(0.5f * y * (1.f + erff(y * 0.70710678f)));
    y = (v.z - mean) * inv * g4.z + b4.z; o.z = roundtf(0.5f * y * (1.f + erff(y * 0.70710678f)));
    y = (v.w - mean) * inv * g4.w + b4.w; o.w = roundtf(0.5f * y * (1.f + erff(y * 0.70710678f)));
    *(float4*)&g_h1[(size_t)r * 1024 + t * 4] = o;
}

// ------------------------------------------------------------- launcher ----
extern "C" void kernel_launch(void* const* d_in, const int* in_sizes, int n_in,
                              void* d_out, int out_size)
{
    const float* x      = (const float*)d_in[0];
    const float* freqs  = (const float*)d_in[1];
    const float* wqkv_w = (const float*)d_in[2];
    const float* wqkv_b = (const float*)d_in[3];
    const float* out_w  = (const float*)d_in[4];
    const float* out_b  = (const float*)d_in[5];
    const float* ffn1_w = (const float*)d_in[6];
    const float* ffn1_b = (const float*)d_in[7];
    const float* ln_g   = (const float*)d_in[8];
    const float* ln_b   = (const float*)d_in[9];
    const float* ffn2_w = (const float*)d_in[10];
    const float* ffn2_b = (const float*)d_in[11];
    float* out = (float*)d_out;

    float *p_qkv, *p_hcat, *p_h1, *p_wr;
    uint32_t *p_xb, *p_ab, *p_wqkvb, *p_woutb;
    cudaGetSymbolAddress((void**)&p_qkv,   g_qkv);
    cudaGetSymbolAddress((void**)&p_hcat,  g_hcat);
    cudaGetSymbolAddress((void**)&p_h1,    g_h1);
    cudaGetSymbolAddress((void**)&p_wr,    g_wr);
    cudaGetSymbolAddress((void**)&p_xb,    g_xb);
    cudaGetSymbolAddress((void**)&p_ab,    g_ab);
    cudaGetSymbolAddress((void**)&p_wqkvb, g_wqkvb);
    cudaGetSymbolAddress((void**)&p_woutb, g_woutb);

    cudaFuncSetAttribute(gemm_tf32,
                         cudaFuncAttributeMaxDynamicSharedMemorySize, GEMM_SMEM);
    cudaFuncSetAttribute(gemm_bf16,
                         cudaFuncAttributeMaxDynamicSharedMemorySize, BGEMM_SMEM);
    cudaFuncSetAttribute(attn_bf16,
                         cudaFuncAttributeMaxDynamicSharedMemorySize, ATT_SMEM);

    // 0a. round/pack x (hcat left half + bf16 copy)
    round_x<<<(MROWS*DD/4 + 255)/256, 256>>>(x);
    // 0b. weight prep: QKV/out -> bf16 packed transposed; FFN -> tf32 transposed
    transpose_pack_bf16<<<dim3(1536/32, 512/64),  dim3(32,8)>>>(wqkv_w, p_wqkvb, 512, 1536);
    transpose_pack_bf16<<<dim3(512/32,  512/64),  dim3(32,8)>>>(out_w,  p_woutb, 512, 512);
    transpose_round<<<dim3(1024/32, 1024/32), dim3(32,8)>>>(ffn1_w, p_wr + WOFF_FFN1, 1024, 1024);
    transpose_round<<<dim3(512/32,  1024/32), dim3(32,8)>>>(ffn2_w, p_wr + WOFF_FFN2, 1024, 512);

    // 1. QKV projection (bf16): [8192,512] @ [512,1536]
    gemm_bf16<<<dim3(1536/128, MROWS/128), 128, BGEMM_SMEM>>>(
        p_xb, 256, p_wqkvb, 256, p_qkv, 1536, wqkv_b, 256, 0);

    // 2. RoPE -> bf16 Q/K; V transpose -> bf16
    rope_kernel<<<(BB*NN*HH*32 + 255)/256, 256>>>(freqs);
    vtrans_kernel<<<dim3(BB*HH, NN/64), 128>>>();

    // 3. Attention (bf16 mma, cp.async ring; writes packed bf16)
    attn_bf16<<<dim3(NN/128, BB*HH), 256, ATT_SMEM>>>();

    // 4. out-proj (bf16) into hcat right half (tf32-rounded)
    gemm_bf16<<<dim3(512/128, MROWS/128), 128, BGEMM_SMEM>>>(
        p_ab, 256, p_woutb, 256, p_hcat + 512, 1024, out_b, 256, 1);

    // 5. FFN1 (tf32): [8192,1024]@[1024,1024]
    gemm_tf32<<<dim3(1024/GBN, MROWS/GBM), 128, GEMM_SMEM>>>(
        p_hcat, 1024, p_wr + WOFF_FFN1, 1024, p_h1, 1024, ffn1_b, nullptr, 0, 1024, 0);

    // 6. LayerNorm + exact GELU (in place, stores rounded)
    ln_gelu_kernel<<<MROWS, 256>>>(ln_g, ln_b);

    // 7. FFN2 (tf32) + residual: out = x + h1 @ [1024,512] + b
    gemm_tf32<<<dim3(512/GBN, MROWS/GBM), 128, GEMM_SMEM>>>(
        p_h1, 1024, p_wr + WOFF_FFN2, 1024, out, DD, ffn2_b, x, DD, 1024, 0);
}

// round 13
// speedup vs baseline: 1.3411x; 1.3411x over previous
#include <cuda_runtime.h>
#include <cuda_bf16.h>
#include <math.h>
#include <stdint.h>

// Problem constants
#define BB 4
#define NN 2048
#define DD 512
#define HH 8
#define HDIM 64
#define MROWS (BB*NN)          // 8192

// ---------------- scratch (static device globals; no runtime allocation) ---
__device__ float g_qkv[MROWS*1536];
__device__ float g_attn[MROWS*DD];
__device__ float g_hcat[MROWS*1024];
__device__ float g_h1[MROWS*1024];
__device__ float g_xr[MROWS*DD];          // tf32-rounded x
__device__ float g_wr[2621440];           // tf32-rounded weights, [N][K]
__device__ uint32_t g_qb[MROWS*256];      // bf16x2 Q [bh][n][d/2], pre-scaled
__device__ uint32_t g_kb[MROWS*256];      // bf16x2 K [bh][n][d/2]
__device__ uint32_t g_vtb[MROWS*256];     // bf16x2 V^T [bh][d][n/2]

#define WOFF_QKV  0                        // [1536][512]
#define WOFF_OUT  786432                   // [512][512]
#define WOFF_FFN1 1048576                  // [1024][1024]
#define WOFF_FFN2 2097152                  // [512][1024]

// ------------------------------------------------------------ tf32 utils ---
__device__ __forceinline__ uint32_t f2tf32(float x) {
    uint32_t u;
    asm volatile("cvt.rna.tf32.f32 %0, %1;" : "=r"(u) : "f"(x));
    return u;
}
__device__ __forceinline__ float roundtf(float x) {
    return __uint_as_float(f2tf32(x));
}
// pack two f32 -> bf16x2 (lo = a, hi = b)
__device__ __forceinline__ uint32_t pack_bf16(float a, float b) {
    uint32_t r;
    asm("cvt.rn.bf16x2.f32 %0, %1, %2;" : "=r"(r) : "f"(b), "f"(a));
    return r;
}

__device__ __forceinline__ void mma_tf32(float c[4],
                                         const uint32_t a[4],
                                         const uint32_t b[2]) {
    asm volatile(
        "mma.sync.aligned.m16n8k8.row.col.f32.tf32.tf32.f32 "
        "{%0,%1,%2,%3}, {%4,%5,%6,%7}, {%8,%9}, {%0,%1,%2,%3};\n"
        : "+f"(c[0]), "+f"(c[1]), "+f"(c[2]), "+f"(c[3])
        : "r"(a[0]), "r"(a[1]), "r"(a[2]), "r"(a[3]),
          "r"(b[0]), "r"(b[1]));
}

__device__ __forceinline__ void mma_bf16(float c[4],
                                         const uint32_t a[4],
                                         uint32_t b0, uint32_t b1) {
    asm volatile(
        "mma.sync.aligned.m16n8k16.row.col.f32.bf16.bf16.f32 "
        "{%0,%1,%2,%3}, {%4,%5,%6,%7}, {%8,%9}, {%0,%1,%2,%3};\n"
        : "+f"(c[0]), "+f"(c[1]), "+f"(c[2]), "+f"(c[3])
        : "r"(a[0]), "r"(a[1]), "r"(a[2]), "r"(a[3]),
          "r"(b0), "r"(b1));
}

__device__ __forceinline__ void cp_async16(uint32_t saddr, const void* gptr) {
    asm volatile("cp.async.cg.shared.global [%0], [%1], 16;\n"
                 :: "r"(saddr), "l"(gptr));
}
#define CP_COMMIT() asm volatile("cp.async.commit_group;\n" ::: "memory")
#define CP_WAIT1()  asm volatile("cp.async.wait_group 1;\n" ::: "memory")
#define CP_WAIT2()  asm volatile("cp.async.wait_group 2;\n" ::: "memory")

// --------------------------- pre-round x, fill hcat left half --------------
__global__ __launch_bounds__(256) void round_x(const float* __restrict__ x)
{
    int idx = blockIdx.x * blockDim.x + threadIdx.x;  // float4 index
    if (idx >= MROWS*DD/4) return;
    float4 v = ((const float4*)x)[idx];
    v.x = roundtf(v.x); v.y = roundtf(v.y);
    v.z = roundtf(v.z); v.w = roundtf(v.w);
    ((float4*)g_xr)[idx] = v;
    int m = idx >> 7, j = idx & 127;
    ((float4*)g_hcat)[m * 256 + j] = v;
}

// ------------------- transpose + round weights -----------------------------
// src [K][N] -> dst [N][K], tf32-rounded.  grid (N/32, K/32), block (32,8).
__global__ __launch_bounds__(256) void transpose_round(
    const float* __restrict__ src, float* __restrict__ dst, int K, int N)
{
    __shared__ float t[32][33];
    int k0 = blockIdx.y * 32, n0 = blockIdx.x * 32;
    int x = threadIdx.x, y = threadIdx.y;
    #pragma unroll
    for (int j = 0; j < 4; j++)
        t[y + 8*j][x] = src[(size_t)(k0 + y + 8*j) * N + n0 + x];
    __syncthreads();
    #pragma unroll
    for (int j = 0; j < 4; j++)
        dst[(size_t)(n0 + y + 8*j) * K + k0 + x] = roundtf(t[x][y + 8*j]);
}

// ---------------- 4-stage pipelined tf32 GEMM, 64x64 warp tiles ------------
// A [M][K] pad 20; Bt [N][K] pad 20.  All fragment loads LDS.32 at banks
// (20*row_group + tg) — conflict-free for both A and B.
#define GBM 128
#define GBN 128
#define GBK 16
#define APADW 20
#define BPADW 20
#define BOFF_W (GBM*APADW)                    // 2560 words
#define STAGE_W (GBM*APADW + GBN*BPADW)       // 5120 words
#define STAGE_B (STAGE_W*4)                   // 20480 bytes
#define GEMM_SMEM (4*STAGE_B)                 // 81920 bytes

__global__ __launch_bounds__(128) void gemm_tf32(
    const float* __restrict__ A, int lda,
    const float* __restrict__ Bt, int ldb,
    float* __restrict__ C, int ldc,
    const float* __restrict__ bias,
    const float* __restrict__ res, int ldres,
    int K, int roundC)
{
    extern __shared__ uint32_t gsm[];
    const uint32_t sbase = (uint32_t)__cvta_generic_to_shared(gsm);

    const int tid  = threadIdx.x;
    const int brow = blockIdx.y * GBM;
    const int bcol = blockIdx.x * GBN;
    const int w    = tid >> 5;
    const int lane = tid & 31;
    const int g    = lane >> 2;
    const int tg   = lane & 3;
    const int wm   = (w & 1) * 64;
    const int wn   = (w >> 1) * 64;

    int arow[4], achk[4];
    uint32_t offA[4], offB[4];
    #pragma unroll
    for (int i = 0; i < 4; i++) {
        int idx = tid + i * 128;         // 0..511
        arow[i] = idx >> 2;
        achk[i] = (idx & 3) * 4;
        offA[i] = (uint32_t)(arow[i] * APADW + achk[i]) * 4;
        offB[i] = (uint32_t)(BOFF_W + arow[i] * BPADW + achk[i]) * 4;
    }

    float acc[4][8][4];
    #pragma unroll
    for (int mi = 0; mi < 4; mi++)
        #pragma unroll
        for (int ni = 0; ni < 8; ni++)
            #pragma unroll
            for (int q = 0; q < 4; q++) acc[mi][ni][q] = 0.f;

    const int nk = K / GBK;

    #pragma unroll
    for (int s = 0; s < 3; s++) {
        const uint32_t sb = sbase + s * STAGE_B;
        const int k0 = s * GBK;
        #pragma unroll
        for (int i = 0; i < 4; i++) {
            cp_async16(sb + offA[i], &A[(size_t)(brow + arow[i]) * lda + k0 + achk[i]]);
            cp_async16(sb + offB[i], &Bt[(size_t)(bcol + arow[i]) * ldb + k0 + achk[i]]);
        }
        CP_COMMIT();
    }

    for (int kt = 0; kt < nk; kt++) {
        CP_WAIT2();
        __syncthreads();
        if (kt + 3 < nk) {
            const uint32_t sb = sbase + ((kt + 3) & 3) * STAGE_B;
            const int k0 = (kt + 3) * GBK;
            #pragma unroll
            for (int i = 0; i < 4; i++) {
                cp_async16(sb + offA[i], &A[(size_t)(brow + arow[i]) * lda + k0 + achk[i]]);
                cp_async16(sb + offB[i], &Bt[(size_t)(bcol + arow[i]) * ldb + k0 + achk[i]]);
            }
        }
        CP_COMMIT();   // always commit: keeps group-count invariant

        const uint32_t* Asb = gsm + (kt & 3) * STAGE_W;
        const uint32_t* Bsb = Asb + BOFF_W;

        #pragma unroll
        for (int ks = 0; ks < 2; ks++) {
            const int kk = ks * 8;
            uint32_t af[4][4], bf[8][2];
            #pragma unroll
            for (int mi = 0; mi < 4; mi++) {
                int r = wm + mi * 16 + g;
                af[mi][0] = Asb[r * APADW + kk + tg];
                af[mi][1] = Asb[(r + 8) * APADW + kk + tg];
                af[mi][2] = Asb[r * APADW + kk + tg + 4];
                af[mi][3] = Asb[(r + 8) * APADW + kk + tg + 4];
            }
            #pragma unroll
            for (int ni = 0; ni < 8; ni++) {
                int c = wn + ni * 8 + g;
                bf[ni][0] = Bsb[c * BPADW + kk + tg];
                bf[ni][1] = Bsb[c * BPADW + kk + tg + 4];
            }
            #pragma unroll
            for (int mi = 0; mi < 4; mi++)
                #pragma unroll
                for (int ni = 0; ni < 8; ni++)
                    mma_tf32(acc[mi][ni], af[mi], bf[ni]);
        }
    }

    #pragma unroll
    for (int mi = 0; mi < 4; mi++) {
        int r0 = brow + wm + mi * 16 + g;
        int r1 = r0 + 8;
        #pragma unroll
        for (int ni = 0; ni < 8; ni++) {
            int cc = bcol + wn + ni * 8 + tg * 2;
            float2 b2 = *(const float2*)&bias[cc];
            float v0 = acc[mi][ni][0] + b2.x;
            float v1 = acc[mi][ni][1] + b2.y;
            float v2 = acc[mi][ni][2] + b2.x;
            float v3 = acc[mi][ni][3] + b2.y;
            if (res) {
                float2 ra = *(const float2*)&res[(size_t)r0 * ldres + cc];
                float2 rb = *(const float2*)&res[(size_t)r1 * ldres + cc];
                v0 += ra.x; v1 += ra.y; v2 += rb.x; v3 += rb.y;
            }
            if (roundC) {
                v0 = roundtf(v0); v1 = roundtf(v1);
                v2 = roundtf(v2); v3 = roundtf(v3);
            }
            *(float2*)&C[(size_t)r0 * ldc + cc] = make_float2(v0, v1);
            *(float2*)&C[(size_t)r1 * ldc + cc] = make_float2(v2, v3);
        }
    }
}

// ------------------------------------------------------------ RoPE split ---
__global__ void rope_kernel(const float* __restrict__ freqs)
{
    int idx = blockIdx.x * blockDim.x + threadIdx.x;
    if (idx >= BB * NN * HH * 32) return;
    int i = idx & 31;
    int h = (idx >> 5) & 7;
    int n = (idx >> 8) & 2047;
    int b = idx >> 19;

    float f = freqs[(b * NN + n) * 32 + i];
    float c = cosf(f), s = sinf(f);

    int base = (b * NN + n) * 1536 + h * 64;
    int ow   = ((b * HH + h) * NN + n) * 32 + i;

    float q1 = g_qkv[base + 2*i], q2 = g_qkv[base + 2*i + 1];
    g_qb[ow] = pack_bf16((q1 * c - q2 * s) * 0.125f,
                         (q1 * s + q2 * c) * 0.125f);

    float k1 = g_qkv[base + 512 + 2*i], k2 = g_qkv[base + 512 + 2*i + 1];
    g_kb[ow] = pack_bf16(k1 * c - k2 * s, k1 * s + k2 * c);
}

// ----------------------------------------------- V transpose to bf16x2 -----
__global__ __launch_bounds__(128) void vtrans_kernel()
{
    __shared__ float ts[64 * 65];
    const int bh = blockIdx.x;
    const int b = bh >> 3, h = bh & 7;
    const int n0 = blockIdx.y * 64;
    const int tid = threadIdx.x;

    {
        const int r = tid >> 1, cb = (tid & 1) * 32;
        const float* src = g_qkv + (size_t)(b * NN + n0 + r) * 1536 + 1024 + h * 64 + cb;
        #pragma unroll
        for (int c = 0; c < 8; c++) {
            float4 v = *(const float4*)&src[c * 4];
            float* d = &ts[r * 65 + cb + c * 4];
            d[0] = v.x; d[1] = v.y; d[2] = v.z; d[3] = v.w;
        }
    }
    __syncthreads();

    const int wp = tid >> 5, p = tid & 31;
    #pragma unroll
    for (int it = 0; it < 16; it++) {
        const int d = wp + it * 4;
        uint32_t word = pack_bf16(ts[(2 * p) * 65 + d], ts[(2 * p + 1) * 65 + d]);
        g_vtb[(size_t)(bh * 64 + d) * 1024 + (n0 >> 1) + p] = word;
    }
}

// ---------------------------- bf16 flash attention, cp.async 3-stage ring --
#define VSW 36
#define STG_W (64 * VSW * 2)
#define VOFF_B (64 * VSW * 4)
#define ATT_SMEM (3 * STG_W * 4)       // 55296 B

__global__ __launch_bounds__(256, 2) void attn_bf16()
{
    extern __shared__ uint32_t sm[];
    const uint32_t sbase = (uint32_t)__cvta_generic_to_shared(sm);

    const int bh = blockIdx.y;
    const int q0 = blockIdx.x * 128;
    const uint32_t* __restrict__ Qw = g_qb + (size_t)bh * NN * 32;
    const uint32_t* __restrict__ Kw = g_kb + (size_t)bh * NN * 32;
    const uint32_t* __restrict__ Vw = g_vtb + (size_t)bh * 64 * 1024;

    const int tid  = threadIdx.x;
    const int w    = tid >> 5;
    const int lane = tid & 31;
    const int g    = lane >> 2;
    const int tg   = lane & 3;
    const int w16  = w * 16;

    uint32_t qa[4][4];
    {
        const int r0 = q0 + w16 + g, r1 = r0 + 8;
        #pragma unroll
        for (int ks = 0; ks < 4; ks++) {
            qa[ks][0] = Qw[r0 * 32 + ks * 8 + tg];
            qa[ks][1] = Qw[r1 * 32 + ks * 8 + tg];
            qa[ks][2] = Qw[r0 * 32 + ks * 8 + tg + 4];
            qa[ks][3] = Qw[r1 * 32 + ks * 8 + tg + 4];
        }
    }

    const int row0 = tid >> 3;
    const int cc   = (tid & 7) * 4;
    const uint32_t dst0 = (uint32_t)(row0 * VSW + cc) * 4;
    const uint32_t dst1 = (uint32_t)((row0 + 32) * VSW + cc) * 4;

    float m0 = -1e30f, m1 = -1e30f, l0 = 0.f, l1 = 0.f;
    float oacc[8][4];
    #pragma unroll
    for (int nt = 0; nt < 8; nt++)
        #pragma unroll
        for (int q = 0; q < 4; q++) oacc[nt][q] = 0.f;

    #pragma unroll
    for (int s = 0; s < 2; s++) {
        const uint32_t sb = sbase + s * STG_W * 4;
        const int k0 = s * 64;
        cp_async16(sb + dst0, Kw + (k0 + row0) * 32 + cc);
        cp_async16(sb + dst1, Kw + (k0 + row0 + 32) * 32 + cc);
        cp_async16(sb + VOFF_B + dst0, Vw + row0 * 1024 + (k0 >> 1) + cc);
        cp_async16(sb + VOFF_B + dst1, Vw + (row0 + 32) * 1024 + (k0 >> 1) + cc);
        CP_COMMIT();
    }

    int stage = 0;
    for (int kt = 0; kt < 32; kt++) {
        CP_WAIT1();
        __syncthreads();
        if (kt + 2 < 32) {
            const int s2 = (stage + 2 >= 3) ? stage - 1 : stage + 2;
            const uint32_t sb = sbase + s2 * STG_W * 4;
            const int k0 = (kt + 2) * 64;
            cp_async16(sb + dst0, Kw + (k0 + row0) * 32 + cc);
            cp_async16(sb + dst1, Kw + (k0 + row0 + 32) * 32 + cc);
            cp_async16(sb + VOFF_B + dst0, Vw + row0 * 1024 + (k0 >> 1) + cc);
            cp_async16(sb + VOFF_B + dst1, Vw + (row0 + 32) * 1024 + (k0 >> 1) + cc);
        }
        CP_COMMIT();

        const uint32_t* Ks  = sm + stage * STG_W;
        const uint32_t* Vst = Ks + 64 * VSW;
        stage = (stage + 1 == 3) ? 0 : stage + 1;

        float sacc[8][4];
        #pragma unroll
        for (int nt = 0; nt < 8; nt++)
            #pragma unroll
            for (int q = 0; q < 4; q++) sacc[nt][q] = 0.f;

        #pragma unroll
        for (int ks = 0; ks < 4; ks++) {
            const int wb = ks * 8;
            #pragma unroll
            for (int nt = 0; nt < 8; nt++) {
                const uint32_t* row = &Ks[(nt * 8 + g) * VSW];
                mma_bf16(sacc[nt], qa[ks], row[wb + tg], row[wb + 4 + tg]);
            }
        }

        float mt0 = -1e30f, mt1 = -1e30f;
        #pragma unroll
        for (int nt = 0; nt < 8; nt++) {
            mt0 = fmaxf(mt0, fmaxf(sacc[nt][0], sacc[nt][1]));
            mt1 = fmaxf(mt1, fmaxf(sacc[nt][2], sacc[nt][3]));
        }
        mt0 = fmaxf(mt0, __shfl_xor_sync(0xffffffffu, mt0, 1));
        mt0 = fmaxf(mt0, __shfl_xor_sync(0xffffffffu, mt0, 2));
        mt1 = fmaxf(mt1, __shfl_xor_sync(0xffffffffu, mt1, 1));
        mt1 = fmaxf(mt1, __shfl_xor_sync(0xffffffffu, mt1, 2));
        float mn0 = fmaxf(m0, mt0), mn1 = fmaxf(m1, mt1);

        float rs0 = 0.f, rs1 = 0.f;
        #pragma unroll
        for (int nt = 0; nt < 8; nt++) {
            sacc[nt][0] = __expf(sacc[nt][0] - mn0);
            sacc[nt][1] = __expf(sacc[nt][1] - mn0);
            sacc[nt][2] = __expf(sacc[nt][2] - mn1);
            sacc[nt][3] = __expf(sacc[nt][3] - mn1);
            rs0 += sacc[nt][0] + sacc[nt][1];
            rs1 += sacc[nt][2] + sacc[nt][3];
        }
        rs0 += __shfl_xor_sync(0xffffffffu, rs0, 1);
        rs0 += __shfl_xor_sync(0xffffffffu, rs0, 2);
        rs1 += __shfl_xor_sync(0xffffffffu, rs1, 1);
        rs1 += __shfl_xor_sync(0xffffffffu, rs1, 2);

        float c0 = __expf(m0 - mn0), c1 = __expf(m1 - mn1);
        l0 = l0 * c0 + rs0;  l1 = l1 * c1 + rs1;
        m0 = mn0;            m1 = mn1;
        #pragma unroll
        for (int nt = 0; nt < 8; nt++) {
            oacc[nt][0] *= c0; oacc[nt][1] *= c0;
            oacc[nt][2] *= c1; oacc[nt][3] *= c1;
        }

        uint32_t pa[8][2];
        #pragma unroll
        for (int nt = 0; nt < 8; nt++) {
            pa[nt][0] = pack_bf16(sacc[nt][0], sacc[nt][1]);
            pa[nt][1] = pack_bf16(sacc[nt][2], sacc[nt][3]);
        }

        #pragma unroll
        for (int ks = 0; ks < 4; ks++) {
            const int wb = ks * 8;
            uint32_t a[4] = { pa[2*ks][0], pa[2*ks][1],
                              pa[2*ks+1][0], pa[2*ks+1][1] };
            #pragma unroll
            for (int nt = 0; nt < 8; nt++) {
                const uint32_t* row = &Vst[(nt * 8 + g) * VSW];
                mma_bf16(oacc[nt], a, row[wb + tg], row[wb + 4 + tg]);
            }
        }
    }

    const int b = bh >> 3, h = bh & 7;
    const float inv0 = 1.f / l0, inv1 = 1.f / l1;
    const int r0 = q0 + w16 + g, r1 = r0 + 8;
    #pragma unroll
    for (int nt = 0; nt < 8; nt++) {
        int d = h * 64 + nt * 8 + tg * 2;
        *(float2*)&g_attn[(size_t)(b * NN + r0) * DD + d] =
            make_float2(roundtf(oacc[nt][0] * inv0), roundtf(oacc[nt][1] * inv0));
        *(float2*)&g_attn[(size_t)(b * NN + r1) * DD + d] =
            make_float2(roundtf(oacc[nt][2] * inv1), roundtf(oacc[nt][3] * inv1));
    }
}

// ------------------------------------------------------- LayerNorm + GELU --
__global__ __launch_bounds__(256) void ln_gelu_kernel(
    const float* __restrict__ gamma, const float* __restrict__ beta)
{
    const int r = blockIdx.x;
    const int t = threadIdx.x;
    float4 v = *(const float4*)&g_h1[(size_t)r * 1024 + t * 4];

    float sum = v.x + v.y + v.z + v.w;
    float sq  = v.x*v.x + v.y*v.y + v.z*v.z + v.w*v.w;
    #pragma unroll
    for (int off = 16; off >= 1; off >>= 1) {
        sum += __shfl_xor_sync(0xffffffffu, sum, off);
        sq  += __shfl_xor_sync(0xffffffffu, sq, off);
    }
    __shared__ float ssum[8], ssq[8];
    if ((t & 31) == 0) { ssum[t >> 5] = sum; ssq[t >> 5] = sq; }
    __syncthreads();
    float tot = 0.f, totq = 0.f;
    #pragma unroll
    for (int w = 0; w < 8; w++) { tot += ssum[w]; totq += ssq[w]; }

    float mean = tot * (1.f / 1024.f);
    float var  = totq * (1.f / 1024.f) - mean * mean;
    float inv  = rsqrtf(var + 1e-5f);

    float4 g4 = *(const float4*)&gamma[t * 4];
    float4 b4 = *(const float4*)&beta[t * 4];
    float y; float4 o;
    y = (v.x - mean) * inv * g4.x + b4.x; o.x = roundtf(0.5f * y * (1.f + erff(y * 0.70710678f)));
    y = (v.y - mean) * inv * g4.y + b4.y; o.y = roundtf(0.5f * y * (1.f + erff(y * 0.70710678f)));
    y = (v.z - mean) * inv * g4.z + b4.z; o.z = roundtf(0.5f * y * (1.f + erff(y * 0.70710678f)));
    y = (v.w - mean) * inv * g4.w + b4.w; o.w = roundtf(0.5f * y * (1.f + erff(y * 0.70710678f)));
    *(float4*)&g_h1[(size_t)r * 1024 + t * 4] = o;
}

// ------------------------------------------------------------- launcher ----
extern "C" void kernel_launch(void* const* d_in, const int* in_sizes, int n_in,
                              void* d_out, int out_size)
{
    const float* x      = (const float*)d_in[0];
    const float* freqs  = (const float*)d_in[1];
    const float* wqkv_w = (const float*)d_in[2];
    const float* wqkv_b = (const float*)d_in[3];
    const float* out_w  = (const float*)d_in[4];
    const float* out_b  = (const float*)d_in[5];
    const float* ffn1_w = (const float*)d_in[6];
    const float* ffn1_b = (const float*)d_in[7];
    const float* ln_g   = (const float*)d_in[8];
    const float* ln_b   = (const float*)d_in[9];
    const float* ffn2_w = (const float*)d_in[10];
    const float* ffn2_b = (const float*)d_in[11];
    float* out = (float*)d_out;

    float *p_qkv, *p_attn, *p_hcat, *p_h1, *p_xr, *p_wr;
    cudaGetSymbolAddress((void**)&p_qkv,  g_qkv);
    cudaGetSymbolAddress((void**)&p_attn, g_attn);
    cudaGetSymbolAddress((void**)&p_hcat, g_hcat);
    cudaGetSymbolAddress((void**)&p_h1,   g_h1);
    cudaGetSymbolAddress((void**)&p_xr,   g_xr);
    cudaGetSymbolAddress((void**)&p_wr,   g_wr);

    cudaFuncSetAttribute(gemm_tf32,
                         cudaFuncAttributeMaxDynamicSharedMemorySize, GEMM_SMEM);
    cudaFuncSetAttribute(attn_bf16,
                         cudaFuncAttributeMaxDynamicSharedMemorySize, ATT_SMEM);

    // 0a. round x, fill hcat left half
    round_x<<<(MROWS*DD/4 + 255)/256, 256>>>(x);
    // 0b. transpose + round weights ([K][N] -> [N][K])
    transpose_round<<<dim3(1536/32, 512/32),  dim3(32,8)>>>(wqkv_w, p_wr + WOFF_QKV, 512, 1536);
    transpose_round<<<dim3(512/32,  512/32),  dim3(32,8)>>>(out_w,  p_wr + WOFF_OUT, 512, 512);
    transpose_round<<<dim3(1024/32, 1024/32), dim3(32,8)>>>(ffn1_w, p_wr + WOFF_FFN1, 1024, 1024);
    transpose_round<<<dim3(512/32,  1024/32), dim3(32,8)>>>(ffn2_w, p_wr + WOFF_FFN2, 1024, 512);

    // 1. QKV projection: [8192,512] @ [512,1536]
    gemm_tf32<<<dim3(1536/GBN, MROWS/GBM), 128, GEMM_SMEM>>>(
        p_xr, DD, p_wr + WOFF_QKV, 512, p_qkv, 1536, wqkv_b, nullptr, 0, DD, 0);

    // 2. RoPE -> bf16 Q/K; V transpose -> bf16
    rope_kernel<<<(BB*NN*HH*32 + 255)/256, 256>>>(freqs);
    vtrans_kernel<<<dim3(BB*HH, NN/64), 128>>>();

    // 3. Attention (bf16 mma, cp.async 3-stage ring)
    attn_bf16<<<dim3(NN/128, BB*HH), 256, ATT_SMEM>>>();

    // 4. out-proj into hcat right half (rounded): [8192,512]@[512,512]
    gemm_tf32<<<dim3(512/GBN, MROWS/GBM), 128, GEMM_SMEM>>>(
        p_attn, DD, p_wr + WOFF_OUT, 512, p_hcat + 512, 1024, out_b, nullptr, 0, DD, 1);

    // 5. FFN1: [8192,1024]@[1024,1024]
    gemm_tf32<<<dim3(1024/GBN, MROWS/GBM), 128, GEMM_SMEM>>>(
        p_hcat, 1024, p_wr + WOFF_FFN1, 1024, p_h1, 1024, ffn1_b, nullptr, 0, 1024, 0);

    // 6. LayerNorm + exact GELU (in place, stores rounded)
    ln_gelu_kernel<<<MROWS, 256>>>(ln_g, ln_b);

    // 7. FFN2 + residual: out = x + h1 @ [1024,512] + b
    gemm_tf32<<<dim3(512/GBN, MROWS/GBM), 128, GEMM_SMEM>>>(
        p_h1, 1024, p_wr + WOFF_FFN2, 1024, out, DD, ffn2_b, x, DD, 1024, 0);
}

// round 14
// speedup vs baseline: 1.4767x; 1.1012x over previous
#include <cuda_runtime.h>
#include <cuda_bf16.h>
#include <math.h>
#include <stdint.h>

// Problem constants
#define BB 4
#define NN 2048
#define DD 512
#define HH 8
#define HDIM 64
#define MROWS (BB*NN)          // 8192

// ---------------- scratch (static device globals; no runtime allocation) ---
__device__ float g_qkv[MROWS*1536];
__device__ float g_attn[MROWS*DD];
__device__ float g_hcat[MROWS*1024];
__device__ float g_h1[MROWS*1024];
__device__ float g_xr[MROWS*DD];          // tf32-rounded x
__device__ float g_wr[2621440];           // tf32-rounded weights, [N][K], pi-permuted K
__device__ uint32_t g_qb[MROWS*256];      // bf16x2 Q [bh][n][d/2], pre-scaled
__device__ uint32_t g_kb[MROWS*256];      // bf16x2 K [bh][n][d/2], pi-permuted words
__device__ uint32_t g_vtb[MROWS*256];     // bf16x2 V^T [bh][d][n/2], pi-permuted words

#define WOFF_QKV  0                        // [1536][512]
#define WOFF_OUT  786432                   // [512][512]
#define WOFF_FFN1 1048576                  // [1024][1024]
#define WOFF_FFN2 2097152                  // [512][1024]

// pi within 8-word groups: (w&~7)|((w&3)<<1)|((w>>2)&1)
#define PI8(w) (((w) & ~7) | (((w) & 3) << 1) | (((w) >> 2) & 1))

// ------------------------------------------------------------ tf32 utils ---
__device__ __forceinline__ uint32_t f2tf32(float x) {
    uint32_t u;
    asm volatile("cvt.rna.tf32.f32 %0, %1;" : "=r"(u) : "f"(x));
    return u;
}
__device__ __forceinline__ float roundtf(float x) {
    return __uint_as_float(f2tf32(x));
}
// pack two f32 -> bf16x2 (lo = a, hi = b)
__device__ __forceinline__ uint32_t pack_bf16(float a, float b) {
    uint32_t r;
    asm("cvt.rn.bf16x2.f32 %0, %1, %2;" : "=r"(r) : "f"(b), "f"(a));
    return r;
}

__device__ __forceinline__ void mma_tf32(float c[4],
                                         const uint32_t a[4],
                                         const uint32_t b[2]) {
    asm volatile(
        "mma.sync.aligned.m16n8k8.row.col.f32.tf32.tf32.f32 "
        "{%0,%1,%2,%3}, {%4,%5,%6,%7}, {%8,%9}, {%0,%1,%2,%3};\n"
        : "+f"(c[0]), "+f"(c[1]), "+f"(c[2]), "+f"(c[3])
        : "r"(a[0]), "r"(a[1]), "r"(a[2]), "r"(a[3]),
          "r"(b[0]), "r"(b[1]));
}

__device__ __forceinline__ void mma_bf16(float c[4],
                                         const uint32_t a[4],
                                         uint32_t b0, uint32_t b1) {
    asm volatile(
        "mma.sync.aligned.m16n8k16.row.col.f32.bf16.bf16.f32 "
        "{%0,%1,%2,%3}, {%4,%5,%6,%7}, {%8,%9}, {%0,%1,%2,%3};\n"
        : "+f"(c[0]), "+f"(c[1]), "+f"(c[2]), "+f"(c[3])
        : "r"(a[0]), "r"(a[1]), "r"(a[2]), "r"(a[3]),
          "r"(b0), "r"(b1));
}

__device__ __forceinline__ void cp_async16(uint32_t saddr, const void* gptr) {
    asm volatile("cp.async.cg.shared.global [%0], [%1], 16;\n"
                 :: "r"(saddr), "l"(gptr));
}
#define CP_COMMIT() asm volatile("cp.async.commit_group;\n" ::: "memory")
#define CP_WAIT1()  asm volatile("cp.async.wait_group 1;\n" ::: "memory")
#define CP_WAIT2()  asm volatile("cp.async.wait_group 2;\n" ::: "memory")

// --------------------------- pre-round x, fill hcat left half --------------
__global__ __launch_bounds__(256) void round_x(const float* __restrict__ x)
{
    int idx = blockIdx.x * blockDim.x + threadIdx.x;  // float4 index
    if (idx >= MROWS*DD/4) return;
    float4 v = ((const float4*)x)[idx];
    v.x = roundtf(v.x); v.y = roundtf(v.y);
    v.z = roundtf(v.z); v.w = roundtf(v.w);
    ((float4*)g_xr)[idx] = v;
    int m = idx >> 7, j = idx & 127;
    ((float4*)g_hcat)[m * 256 + j] = v;
}

// ------------------- transpose + round + pi-permute weights ----------------
// src [K][N] -> dst [N][K] with K words permuted within 8-groups.
// grid (N/32, K/32), block (32,8).  (R10-verified layout.)
__global__ __launch_bounds__(256) void transpose_round_pi(
    const float* __restrict__ src, float* __restrict__ dst, int K, int N)
{
    __shared__ float t[32][33];
    int k0 = blockIdx.y * 32, n0 = blockIdx.x * 32;
    int x = threadIdx.x, y = threadIdx.y;
    #pragma unroll
    for (int j = 0; j < 4; j++)
        t[y + 8*j][x] = src[(size_t)(k0 + y + 8*j) * N + n0 + x];
    __syncthreads();
    const int px = PI8(x);
    #pragma unroll
    for (int j = 0; j < 4; j++)
        dst[(size_t)(n0 + y + 8*j) * K + k0 + px] = roundtf(t[x][y + 8*j]);
}

// ---------------- 4-stage pipelined tf32 GEMM, 64x64 warp tiles (R10) ------
// A [M][K] natural layout, pad 20.  Bt [N][K] pi-permuted K, pad 24
// -> B-fragment pairs adjacent (LDS.64), conflict-free under phasing.
#define GBM 128
#define GBN 128
#define GBK 16
#define APADW 20
#define BPADW 24
#define BOFF_W (GBM*APADW)                    // 2560 words
#define STAGE_W (GBM*APADW + GBN*BPADW)       // 5632 words
#define STAGE_B (STAGE_W*4)                   // 22528 bytes
#define GEMM_SMEM (4*STAGE_B)                 // 90112 bytes

__global__ __launch_bounds__(128) void gemm_tf32(
    const float* __restrict__ A, int lda,
    const float* __restrict__ Bt, int ldb,
    float* __restrict__ C, int ldc,
    const float* __restrict__ bias,
    const float* __restrict__ res, int ldres,
    int K, int roundC)
{
    extern __shared__ uint32_t gsm[];
    const uint32_t sbase = (uint32_t)__cvta_generic_to_shared(gsm);

    const int tid  = threadIdx.x;
    const int brow = blockIdx.y * GBM;
    const int bcol = blockIdx.x * GBN;
    const int w    = tid >> 5;
    const int lane = tid & 31;
    const int g    = lane >> 2;
    const int tg   = lane & 3;
    const int wm   = (w & 1) * 64;
    const int wn   = (w >> 1) * 64;

    int arow[4], achk[4];
    uint32_t offA[4], offB[4];
    #pragma unroll
    for (int i = 0; i < 4; i++) {
        int idx = tid + i * 128;         // 0..511
        arow[i] = idx >> 2;
        achk[i] = (idx & 3) * 4;
        offA[i] = (uint32_t)(arow[i] * APADW + achk[i]) * 4;
        offB[i] = (uint32_t)(BOFF_W + arow[i] * BPADW + achk[i]) * 4;
    }

    float acc[4][8][4];
    #pragma unroll
    for (int mi = 0; mi < 4; mi++)
        #pragma unroll
        for (int ni = 0; ni < 8; ni++)
            #pragma unroll
            for (int q = 0; q < 4; q++) acc[mi][ni][q] = 0.f;

    const int nk = K / GBK;

    #pragma unroll
    for (int s = 0; s < 3; s++) {
        const uint32_t sb = sbase + s * STAGE_B;
        const int k0 = s * GBK;
        #pragma unroll
        for (int i = 0; i < 4; i++) {
            cp_async16(sb + offA[i], &A[(size_t)(brow + arow[i]) * lda + k0 + achk[i]]);
            cp_async16(sb + offB[i], &Bt[(size_t)(bcol + arow[i]) * ldb + k0 + achk[i]]);
        }
        CP_COMMIT();
    }

    for (int kt = 0; kt < nk; kt++) {
        CP_WAIT2();
        __syncthreads();
        if (kt + 3 < nk) {
            const uint32_t sb = sbase + ((kt + 3) & 3) * STAGE_B;
            const int k0 = (kt + 3) * GBK;
            #pragma unroll
            for (int i = 0; i < 4; i++) {
                cp_async16(sb + offA[i], &A[(size_t)(brow + arow[i]) * lda + k0 + achk[i]]);
                cp_async16(sb + offB[i], &Bt[(size_t)(bcol + arow[i]) * ldb + k0 + achk[i]]);
            }
        }
        CP_COMMIT();   // always commit: keeps group-count invariant

        const uint32_t* Asb = gsm + (kt & 3) * STAGE_W;
        const uint32_t* Bsb = Asb + BOFF_W;

        #pragma unroll
        for (int ks = 0; ks < 2; ks++) {
            const int kk = ks * 8;
            uint32_t af[4][4], bf[8][2];
            #pragma unroll
            for (int mi = 0; mi < 4; mi++) {
                int r = wm + mi * 16 + g;
                af[mi][0] = Asb[r * APADW + kk + tg];
                af[mi][1] = Asb[(r + 8) * APADW + kk + tg];
                af[mi][2] = Asb[r * APADW + kk + tg + 4];
                af[mi][3] = Asb[(r + 8) * APADW + kk + tg + 4];
            }
            #pragma unroll
            for (int ni = 0; ni < 8; ni++) {
                int c = wn + ni * 8 + g;
                uint2 bv = *(const uint2*)&Bsb[c * BPADW + kk + 2 * tg];
                bf[ni][0] = bv.x; bf[ni][1] = bv.y;
            }
            #pragma unroll
            for (int mi = 0; mi < 4; mi++)
                #pragma unroll
                for (int ni = 0; ni < 8; ni++)
                    mma_tf32(acc[mi][ni], af[mi], bf[ni]);
        }
    }

    #pragma unroll
    for (int mi = 0; mi < 4; mi++) {
        int r0 = brow + wm + mi * 16 + g;
        int r1 = r0 + 8;
        #pragma unroll
        for (int ni = 0; ni < 8; ni++) {
            int cc = bcol + wn + ni * 8 + tg * 2;
            float2 b2 = *(const float2*)&bias[cc];
            float v0 = acc[mi][ni][0] + b2.x;
            float v1 = acc[mi][ni][1] + b2.y;
            float v2 = acc[mi][ni][2] + b2.x;
            float v3 = acc[mi][ni][3] + b2.y;
            if (res) {
                float2 ra = *(const float2*)&res[(size_t)r0 * ldres + cc];
                float2 rb = *(const float2*)&res[(size_t)r1 * ldres + cc];
                v0 += ra.x; v1 += ra.y; v2 += rb.x; v3 += rb.y;
            }
            if (roundC) {
                v0 = roundtf(v0); v1 = roundtf(v1);
                v2 = roundtf(v2); v3 = roundtf(v3);
            }
            *(float2*)&C[(size_t)r0 * ldc + cc] = make_float2(v0, v1);
            *(float2*)&C[(size_t)r1 * ldc + cc] = make_float2(v2, v3);
        }
    }
}

// ------------------------------------------------------------ RoPE split ---
// Q unpermuted (A-operand); K words pi-permuted (B-operand -> LDS.64 frags).
__global__ void rope_kernel(const float* __restrict__ freqs)
{
    int idx = blockIdx.x * blockDim.x + threadIdx.x;
    if (idx >= BB * NN * HH * 32) return;
    int i = idx & 31;
    int h = (idx >> 5) & 7;
    int n = (idx >> 8) & 2047;
    int b = idx >> 19;

    float f = freqs[(b * NN + n) * 32 + i];
    float c = cosf(f), s = sinf(f);

    int base = (b * NN + n) * 1536 + h * 64;
    int rowb = ((b * HH + h) * NN + n) * 32;

    float q1 = g_qkv[base + 2*i], q2 = g_qkv[base + 2*i + 1];
    g_qb[rowb + i] = pack_bf16((q1 * c - q2 * s) * 0.125f,
                               (q1 * s + q2 * c) * 0.125f);

    float k1 = g_qkv[base + 512 + 2*i], k2 = g_qkv[base + 512 + 2*i + 1];
    g_kb[rowb + PI8(i)] = pack_bf16(k1 * c - k2 * s, k1 * s + k2 * c);
}

// ----------------------------------------------- V transpose to bf16x2 -----
// g_qkv V section [n][d] -> g_vtb [bh][d][n/2], key-pair words pi-permuted
// within each 32-word (64-key) tile chunk.
__global__ __launch_bounds__(128) void vtrans_kernel()
{
    __shared__ float ts[64 * 65];
    const int bh = blockIdx.x;
    const int b = bh >> 3, h = bh & 7;
    const int n0 = blockIdx.y * 64;
    const int tid = threadIdx.x;

    {
        const int r = tid >> 1, cb = (tid & 1) * 32;
        const float* src = g_qkv + (size_t)(b * NN + n0 + r) * 1536 + 1024 + h * 64 + cb;
        #pragma unroll
        for (int c = 0; c < 8; c++) {
            float4 v = *(const float4*)&src[c * 4];
            float* d = &ts[r * 65 + cb + c * 4];
            d[0] = v.x; d[1] = v.y; d[2] = v.z; d[3] = v.w;
        }
    }
    __syncthreads();

    const int wp = tid >> 5, p = tid & 31;
    const int pp = PI8(p);
    #pragma unroll
    for (int it = 0; it < 16; it++) {
        const int d = wp + it * 4;
        uint32_t word = pack_bf16(ts[(2 * p) * 65 + d], ts[(2 * p + 1) * 65 + d]);
        g_vtb[(size_t)(bh * 64 + d) * 1024 + (n0 >> 1) + pp] = word;
    }
}

// ---------------------------- bf16 flash attention, cp.async 3-stage ring --
// K/V words pi-permuted in gmem -> B-fragments are single LDS.64.
// Row stride VSW=40 words: 40g mod 32 = 8g -> per-phase bank sets
// {0,2,4,6},{8..14},{16..22},{24..30}: conflict-free.
#define VSW 40
#define STG_W (64 * VSW * 2)
#define VOFF_B (64 * VSW * 4)
#define ATT_SMEM (3 * STG_W * 4)       // 61440 B

__global__ __launch_bounds__(256, 2) void attn_bf16()
{
    extern __shared__ uint32_t sm[];
    const uint32_t sbase = (uint32_t)__cvta_generic_to_shared(sm);

    const int bh = blockIdx.y;
    const int q0 = blockIdx.x * 128;
    const uint32_t* __restrict__ Qw = g_qb + (size_t)bh * NN * 32;
    const uint32_t* __restrict__ Kw = g_kb + (size_t)bh * NN * 32;
    const uint32_t* __restrict__ Vw = g_vtb + (size_t)bh * 64 * 1024;

    const int tid  = threadIdx.x;
    const int w    = tid >> 5;
    const int lane = tid & 31;
    const int g    = lane >> 2;
    const int tg   = lane & 3;
    const int w16  = w * 16;

    uint32_t qa[4][4];
    {
        const int r0 = q0 + w16 + g, r1 = r0 + 8;
        #pragma unroll
        for (int ks = 0; ks < 4; ks++) {
            qa[ks][0] = Qw[r0 * 32 + ks * 8 + tg];
            qa[ks][1] = Qw[r1 * 32 + ks * 8 + tg];
            qa[ks][2] = Qw[r0 * 32 + ks * 8 + tg + 4];
            qa[ks][3] = Qw[r1 * 32 + ks * 8 + tg + 4];
        }
    }

    const int row0 = tid >> 3;
    const int cc   = (tid & 7) * 4;
    const uint32_t dst0 = (uint32_t)(row0 * VSW + cc) * 4;
    const uint32_t dst1 = (uint32_t)((row0 + 32) * VSW + cc) * 4;

    float m0 = -1e30f, m1 = -1e30f, l0 = 0.f, l1 = 0.f;
    float oacc[8][4];
    #pragma unroll
    for (int nt = 0; nt < 8; nt++)
        #pragma unroll
        for (int q = 0; q < 4; q++) oacc[nt][q] = 0.f;

    #pragma unroll
    for (int s = 0; s < 2; s++) {
        const uint32_t sb = sbase + s * STG_W * 4;
        const int k0 = s * 64;
        cp_async16(sb + dst0, Kw + (k0 + row0) * 32 + cc);
        cp_async16(sb + dst1, Kw + (k0 + row0 + 32) * 32 + cc);
        cp_async16(sb + VOFF_B + dst0, Vw + row0 * 1024 + (k0 >> 1) + cc);
        cp_async16(sb + VOFF_B + dst1, Vw + (row0 + 32) * 1024 + (k0 >> 1) + cc);
        CP_COMMIT();
    }

    int stage = 0;
    for (int kt = 0; kt < 32; kt++) {
        CP_WAIT1();
        __syncthreads();
        if (kt + 2 < 32) {
            const int s2 = (stage + 2 >= 3) ? stage - 1 : stage + 2;
            const uint32_t sb = sbase + s2 * STG_W * 4;
            const int k0 = (kt + 2) * 64;
            cp_async16(sb + dst0, Kw + (k0 + row0) * 32 + cc);
            cp_async16(sb + dst1, Kw + (k0 + row0 + 32) * 32 + cc);
            cp_async16(sb + VOFF_B + dst0, Vw + row0 * 1024 + (k0 >> 1) + cc);
            cp_async16(sb + VOFF_B + dst1, Vw + (row0 + 32) * 1024 + (k0 >> 1) + cc);
        }
        CP_COMMIT();

        const uint32_t* Ks  = sm + stage * STG_W;
        const uint32_t* Vst = Ks + 64 * VSW;
        stage = (stage + 1 == 3) ? 0 : stage + 1;

        float sacc[8][4];
        #pragma unroll
        for (int nt = 0; nt < 8; nt++)
            #pragma unroll
            for (int q = 0; q < 4; q++) sacc[nt][q] = 0.f;

        #pragma unroll
        for (int ks = 0; ks < 4; ks++) {
            const int wb = ks * 8 + 2 * tg;
            #pragma unroll
            for (int nt = 0; nt < 8; nt++) {
                uint2 bv = *(const uint2*)&Ks[(nt * 8 + g) * VSW + wb];
                mma_bf16(sacc[nt], qa[ks], bv.x, bv.y);
            }
        }

        float mt0 = -1e30f, mt1 = -1e30f;
        #pragma unroll
        for (int nt = 0; nt < 8; nt++) {
            mt0 = fmaxf(mt0, fmaxf(sacc[nt][0], sacc[nt][1]));
            mt1 = fmaxf(mt1, fmaxf(sacc[nt][2], sacc[nt][3]));
        }
        mt0 = fmaxf(mt0, __shfl_xor_sync(0xffffffffu, mt0, 1));
        mt0 = fmaxf(mt0, __shfl_xor_sync(0xffffffffu, mt0, 2));
        mt1 = fmaxf(mt1, __shfl_xor_sync(0xffffffffu, mt1, 1));
        mt1 = fmaxf(mt1, __shfl_xor_sync(0xffffffffu, mt1, 2));
        float mn0 = fmaxf(m0, mt0), mn1 = fmaxf(m1, mt1);

        float rs0 = 0.f, rs1 = 0.f;
        #pragma unroll
        for (int nt = 0; nt < 8; nt++) {
            sacc[nt][0] = __expf(sacc[nt][0] - mn0);
            sacc[nt][1] = __expf(sacc[nt][1] - mn0);
            sacc[nt][2] = __expf(sacc[nt][2] - mn1);
            sacc[nt][3] = __expf(sacc[nt][3] - mn1);
            rs0 += sacc[nt][0] + sacc[nt][1];
            rs1 += sacc[nt][2] + sacc[nt][3];
        }
        rs0 += __shfl_xor_sync(0xffffffffu, rs0, 1);
        rs0 += __shfl_xor_sync(0xffffffffu, rs0, 2);
        rs1 += __shfl_xor_sync(0xffffffffu, rs1, 1);
        rs1 += __shfl_xor_sync(0xffffffffu, rs1, 2);

        float c0 = __expf(m0 - mn0), c1 = __expf(m1 - mn1);
        l0 = l0 * c0 + rs0;  l1 = l1 * c1 + rs1;
        m0 = mn0;            m1 = mn1;
        #pragma unroll
        for (int nt = 0; nt < 8; nt++) {
            oacc[nt][0] *= c0; oacc[nt][1] *= c0;
            oacc[nt][2] *= c1; oacc[nt][3] *= c1;
        }

        uint32_t pa[8][2];
        #pragma unroll
        for (int nt = 0; nt < 8; nt++) {
            pa[nt][0] = pack_bf16(sacc[nt][0], sacc[nt][1]);
            pa[nt][1] = pack_bf16(sacc[nt][2], sacc[nt][3]);
        }

        #pragma unroll
        for (int ks = 0; ks < 4; ks++) {
            const int wb = ks * 8 + 2 * tg;
            uint32_t a[4] = { pa[2*ks][0], pa[2*ks][1],
                              pa[2*ks+1][0], pa[2*ks+1][1] };
            #pragma unroll
            for (int nt = 0; nt < 8; nt++) {
                uint2 bv = *(const uint2*)&Vst[(nt * 8 + g) * VSW + wb];
                mma_bf16(oacc[nt], a, bv.x, bv.y);
            }
        }
    }

    const int b = bh >> 3, h = bh & 7;
    const float inv0 = 1.f / l0, inv1 = 1.f / l1;
    const int r0 = q0 + w16 + g, r1 = r0 + 8;
    #pragma unroll
    for (int nt = 0; nt < 8; nt++) {
        int d = h * 64 + nt * 8 + tg * 2;
        *(float2*)&g_attn[(size_t)(b * NN + r0) * DD + d] =
            make_float2(roundtf(oacc[nt][0] * inv0), roundtf(oacc[nt][1] * inv0));
        *(float2*)&g_attn[(size_t)(b * NN + r1) * DD + d] =
            make_float2(roundtf(oacc[nt][2] * inv1), roundtf(oacc[nt][3] * inv1));
    }
}

// ------------------------------------------------------- LayerNorm + GELU --
__global__ __launch_bounds__(256) void ln_gelu_kernel(
    const float* __restrict__ gamma, const float* __restrict__ beta)
{
    const int r = blockIdx.x;
    const int t = threadIdx.x;
    float4 v = *(const float4*)&g_h1[(size_t)r * 1024 + t * 4];

    float sum = v.x + v.y + v.z + v.w;
    float sq  = v.x*v.x + v.y*v.y + v.z*v.z + v.w*v.w;
    #pragma unroll
    for (int off = 16; off >= 1; off >>= 1) {
        sum += __shfl_xor_sync(0xffffffffu, sum, off);
        sq  += __shfl_xor_sync(0xffffffffu, sq, off);
    }
    __shared__ float ssum[8], ssq[8];
    if ((t & 31) == 0) { ssum[t >> 5] = sum; ssq[t >> 5] = sq; }
    __syncthreads();
    float tot = 0.f, totq = 0.f;
    #pragma unroll
    for (int w = 0; w < 8; w++) { tot += ssum[w]; totq += ssq[w]; }

    float mean = tot * (1.f / 1024.f);
    float var  = totq * (1.f / 1024.f) - mean * mean;
    float inv  = rsqrtf(var + 1e-5f);

    float4 g4 = *(const float4*)&gamma[t * 4];
    float4 b4 = *(const float4*)&beta[t * 4];
    float y; float4 o;
    y = (v.x - mean) * inv * g4.x + b4.x; o.x = roundtf(0.5f * y * (1.f + erff(y * 0.70710678f)));
    y = (v.y - mean) * inv * g4.y + b4.y; o.y = roundtf(0.5f * y * (1.f + erff(y * 0.70710678f)));
    y = (v.z - mean) * inv * g4.z + b4.z; o.z = roundtf(0.5f * y * (1.f + erff(y * 0.70710678f)));
    y = (v.w - mean) * inv * g4.w + b4.w; o.w = roundtf(0.5f * y * (1.f + erff(y * 0.70710678f)));
    *(float4*)&g_h1[(size_t)r * 1024 + t * 4] = o;
}

// ------------------------------------------------------------- launcher ----
extern "C" void kernel_launch(void* const* d_in, const int* in_sizes, int n_in,
                              void* d_out, int out_size)
{
    const float* x      = (const float*)d_in[0];
    const float* freqs  = (const float*)d_in[1];
    const float* wqkv_w = (const float*)d_in[2];
    const float* wqkv_b = (const float*)d_in[3];
    const float* out_w  = (const float*)d_in[4];
    const float* out_b  = (const float*)d_in[5];
    const float* ffn1_w = (const float*)d_in[6];
    const float* ffn1_b = (const float*)d_in[7];
    const float* ln_g   = (const float*)d_in[8];
    const float* ln_b   = (const float*)d_in[9];
    const float* ffn2_w = (const float*)d_in[10];
    const float* ffn2_b = (const float*)d_in[11];
    float* out = (float*)d_out;

    float *p_qkv, *p_attn, *p_hcat, *p_h1, *p_xr, *p_wr;
    cudaGetSymbolAddress((void**)&p_qkv,  g_qkv);
    cudaGetSymbolAddress((void**)&p_attn, g_attn);
    cudaGetSymbolAddress((void**)&p_hcat, g_hcat);
    cudaGetSymbolAddress((void**)&p_h1,   g_h1);
    cudaGetSymbolAddress((void**)&p_xr,   g_xr);
    cudaGetSymbolAddress((void**)&p_wr,   g_wr);

    cudaFuncSetAttribute(gemm_tf32,
                         cudaFuncAttributeMaxDynamicSharedMemorySize, GEMM_SMEM);
    cudaFuncSetAttribute(attn_bf16,
                         cudaFuncAttributeMaxDynamicSharedMemorySize, ATT_SMEM);

    // 0a. round x, fill hcat left half
    round_x<<<(MROWS*DD/4 + 255)/256, 256>>>(x);
    // 0b. transpose + round + pi-permute weights ([K][N] -> [N][K])
    transpose_round_pi<<<dim3(1536/32, 512/32),  dim3(32,8)>>>(wqkv_w, p_wr + WOFF_QKV, 512, 1536);
    transpose_round_pi<<<dim3(512/32,  512/32),  dim3(32,8)>>>(out_w,  p_wr + WOFF_OUT, 512, 512);
    transpose_round_pi<<<dim3(1024/32, 1024/32), dim3(32,8)>>>(ffn1_w, p_wr + WOFF_FFN1, 1024, 1024);
    transpose_round_pi<<<dim3(512/32,  1024/32), dim3(32,8)>>>(ffn2_w, p_wr + WOFF_FFN2, 1024, 512);

    // 1. QKV projection: [8192,512] @ [512,1536]
    gemm_tf32<<<dim3(1536/GBN, MROWS/GBM), 128, GEMM_SMEM>>>(
        p_xr, DD, p_wr + WOFF_QKV, 512, p_qkv, 1536, wqkv_b, nullptr, 0, DD, 0);

    // 2. RoPE -> bf16 Q/K (K pi-permuted); V transpose -> bf16 (pi-permuted)
    rope_kernel<<<(BB*NN*HH*32 + 255)/256, 256>>>(freqs);
    vtrans_kernel<<<dim3(BB*HH, NN/64), 128>>>();

    // 3. Attention (bf16 mma, cp.async 3-stage ring, LDS.64 B-frags)
    attn_bf16<<<dim3(NN/128, BB*HH), 256, ATT_SMEM>>>();

    // 4. out-proj into hcat right half (rounded): [8192,512]@[512,512]
    gemm_tf32<<<dim3(512/GBN, MROWS/GBM), 128, GEMM_SMEM>>>(
        p_attn, DD, p_wr + WOFF_OUT, 512, p_hcat + 512, 1024, out_b, nullptr, 0, DD, 1);

    // 5. FFN1: [8192,1024]@[1024,1024]
    gemm_tf32<<<dim3(1024/GBN, MROWS/GBM), 128, GEMM_SMEM>>>(
        p_hcat, 1024, p_wr + WOFF_FFN1, 1024, p_h1, 1024, ffn1_b, nullptr, 0, 1024, 0);

    // 6. LayerNorm + exact GELU (in place, stores rounded)
    ln_gelu_kernel<<<MROWS, 256>>>(ln_g, ln_b);

    // 7. FFN2 + residual: out = x + h1 @ [1024,512] + b
    gemm_tf32<<<dim3(512/GBN, MROWS/GBM), 128, GEMM_SMEM>>>(
        p_h1, 1024, p_wr + WOFF_FFN2, 1024, out, DD, ffn2_b, x, DD, 1024, 0);
}

// round 15
// speedup vs baseline: 1.5022x; 1.0173x over previous
#include <cuda_runtime.h>
#include <cuda_bf16.h>
#include <math.h>
#include <stdint.h>

// Problem constants
#define BB 4
#define NN 2048
#define DD 512
#define HH 8
#define HDIM 64
#define MROWS (BB*NN)          // 8192

// ---------------- scratch (static device globals; no runtime allocation) ---
__device__ float g_qkv[MROWS*1536];
__device__ float g_attn[MROWS*DD];
__device__ float g_hcat[MROWS*1024];      // scratch (Wc f32 staging)
__device__ float g_h1[MROWS*1024];
__device__ float g_xr[MROWS*DD];          // tf32-rounded x
__device__ float g_wr[2621440];           // tf32-rounded weights, [N][K], pi-permuted K
__device__ float g_wct[524288];           // Wc^T [1024][512], pi-permuted, rounded
__device__ float g_bias2[1024];           // ffn1_b + out_b @ W1_bot
__device__ float g_zero[1024];            // stays zero
__device__ uint32_t g_qb[MROWS*256];      // bf16x2 Q [bh][n][d/2], pre-scaled
__device__ uint32_t g_kb[MROWS*256];      // bf16x2 K, pi-permuted words
__device__ uint32_t g_vtb[MROWS*256];     // bf16x2 V^T, pi-permuted words

#define WOFF_QKV  0                        // [1536][512] pi
#define WOFF_OUT  786432                   // rounded out_w, natural [512][512]
#define WOFF_FFN1 1048576                  // W1top^T [1024][512] pi
#define WOFF_FFN1B (1048576 + 524288)      // W1bot^T [1024][512] pi
#define WOFF_FFN2 2097152                  // [512][1024] pi

// pi within 8-word groups
#define PI8(w) (((w) & ~7) | (((w) & 3) << 1) | (((w) >> 2) & 1))

// ------------------------------------------------------------ tf32 utils ---
__device__ __forceinline__ uint32_t f2tf32(float x) {
    uint32_t u;
    asm volatile("cvt.rna.tf32.f32 %0, %1;" : "=r"(u) : "f"(x));
    return u;
}
__device__ __forceinline__ float roundtf(float x) {
    return __uint_as_float(f2tf32(x));
}
__device__ __forceinline__ uint32_t pack_bf16(float a, float b) {
    uint32_t r;
    asm("cvt.rn.bf16x2.f32 %0, %1, %2;" : "=r"(r) : "f"(b), "f"(a));
    return r;
}

__device__ __forceinline__ void mma_tf32(float c[4],
                                         const uint32_t a[4],
                                         const uint32_t b[2]) {
    asm volatile(
        "mma.sync.aligned.m16n8k8.row.col.f32.tf32.tf32.f32 "
        "{%0,%1,%2,%3}, {%4,%5,%6,%7}, {%8,%9}, {%0,%1,%2,%3};\n"
        : "+f"(c[0]), "+f"(c[1]), "+f"(c[2]), "+f"(c[3])
        : "r"(a[0]), "r"(a[1]), "r"(a[2]), "r"(a[3]),
          "r"(b[0]), "r"(b[1]));
}

__device__ __forceinline__ void mma_bf16(float c[4],
                                         const uint32_t a[4],
                                         uint32_t b0, uint32_t b1) {
    asm volatile(
        "mma.sync.aligned.m16n8k16.row.col.f32.bf16.bf16.f32 "
        "{%0,%1,%2,%3}, {%4,%5,%6,%7}, {%8,%9}, {%0,%1,%2,%3};\n"
        : "+f"(c[0]), "+f"(c[1]), "+f"(c[2]), "+f"(c[3])
        : "r"(a[0]), "r"(a[1]), "r"(a[2]), "r"(a[3]),
          "r"(b0), "r"(b1));
}

__device__ __forceinline__ void cp_async16(uint32_t saddr, const void* gptr) {
    asm volatile("cp.async.cg.shared.global [%0], [%1], 16;\n"
                 :: "r"(saddr), "l"(gptr));
}
#define CP_COMMIT() asm volatile("cp.async.commit_group;\n" ::: "memory")
#define CP_WAIT1()  asm volatile("cp.async.wait_group 1;\n" ::: "memory")
#define CP_WAIT2()  asm volatile("cp.async.wait_group 2;\n" ::: "memory")

// --------------------------- pre-round x -----------------------------------
__global__ __launch_bounds__(256) void round_x(const float* __restrict__ x)
{
    int idx = blockIdx.x * blockDim.x + threadIdx.x;  // float4 index
    if (idx >= MROWS*DD/4) return;
    float4 v = ((const float4*)x)[idx];
    v.x = roundtf(v.x); v.y = roundtf(v.y);
    v.z = roundtf(v.z); v.w = roundtf(v.w);
    ((float4*)g_xr)[idx] = v;
}

// --------------------------- round out_w (natural layout) ------------------
__global__ __launch_bounds__(256) void round_outw(const float* __restrict__ w)
{
    int idx = blockIdx.x * blockDim.x + threadIdx.x;  // float4, 65536 total
    if (idx >= 512*512/4) return;
    float4 v = ((const float4*)w)[idx];
    v.x = roundtf(v.x); v.y = roundtf(v.y);
    v.z = roundtf(v.z); v.w = roundtf(v.w);
    ((float4*)(g_wr + WOFF_OUT))[idx] = v;
}

// ------------------- transpose + round + pi-permute weights ----------------
// src [K][N] (row stride N) -> dst [N][K] with K words pi-permuted.
__global__ __launch_bounds__(256) void transpose_round_pi(
    const float* __restrict__ src, float* __restrict__ dst, int K, int N)
{
    __shared__ float t[32][33];
    int k0 = blockIdx.y * 32, n0 = blockIdx.x * 32;
    int x = threadIdx.x, y = threadIdx.y;
    #pragma unroll
    for (int j = 0; j < 4; j++)
        t[y + 8*j][x] = src[(size_t)(k0 + y + 8*j) * N + n0 + x];
    __syncthreads();
    const int px = PI8(x);
    #pragma unroll
    for (int j = 0; j < 4; j++)
        dst[(size_t)(n0 + y + 8*j) * K + k0 + px] = roundtf(t[x][y + 8*j]);
}

// ------------------- bias2 = ffn1_b + out_b @ W1_bot -----------------------
__global__ __launch_bounds__(256) void bias2_kernel(
    const float* __restrict__ ffn1_w, const float* __restrict__ ffn1_b,
    const float* __restrict__ out_b)
{
    int j = blockIdx.x * 256 + threadIdx.x;   // 0..1023
    float s = ffn1_b[j];
    for (int o = 0; o < 512; o++)
        s += out_b[o] * ffn1_w[(size_t)(512 + o) * 1024 + j];
    g_bias2[j] = s;
}

// -------- 4-stage pipelined tf32 GEMM, 64x64 warp tiles, 2 segments --------
// Segment s: C += A_s[M][K_s] @ B_s[N][K_s]^T.  A pad 20 natural; B pad 24
// pi-permuted K (LDS.64 fragments, conflict-free under half-warp phasing).
#define GBM 128
#define GBN 128
#define GBK 16
#define APADW 20
#define BPADW 24
#define BOFF_W (GBM*APADW)                    // 2560 words
#define STAGE_W (GBM*APADW + GBN*BPADW)       // 5632 words
#define STAGE_B (STAGE_W*4)                   // 22528 bytes
#define GEMM_SMEM (4*STAGE_B)                 // 90112 bytes

__global__ __launch_bounds__(128) void gemm_tf32(
    const float* __restrict__ A1, int lda1,
    const float* __restrict__ B1, int ldb1, int K1,
    const float* __restrict__ A2, int lda2,
    const float* __restrict__ B2, int ldb2, int K2,
    float* __restrict__ C, int ldc,
    const float* __restrict__ bias,
    const float* __restrict__ res, int ldres,
    int roundC)
{
    extern __shared__ uint32_t gsm[];
    const uint32_t sbase = (uint32_t)__cvta_generic_to_shared(gsm);

    const int tid  = threadIdx.x;
    const int brow = blockIdx.y * GBM;
    const int bcol = blockIdx.x * GBN;
    const int w    = tid >> 5;
    const int lane = tid & 31;
    const int g    = lane >> 2;
    const int tg   = lane & 3;
    const int wm   = (w & 1) * 64;
    const int wn   = (w >> 1) * 64;

    int arow[4], achk[4];
    uint32_t offA[4], offB[4];
    #pragma unroll
    for (int i = 0; i < 4; i++) {
        int idx = tid + i * 128;         // 0..511
        arow[i] = idx >> 2;
        achk[i] = (idx & 3) * 4;
        offA[i] = (uint32_t)(arow[i] * APADW + achk[i]) * 4;
        offB[i] = (uint32_t)(BOFF_W + arow[i] * BPADW + achk[i]) * 4;
    }

    float acc[4][8][4];
    #pragma unroll
    for (int mi = 0; mi < 4; mi++)
        #pragma unroll
        for (int ni = 0; ni < 8; ni++)
            #pragma unroll
            for (int q = 0; q < 4; q++) acc[mi][ni][q] = 0.f;

    for (int seg = 0; seg < 2; seg++) {
        const float* A  = seg ? A2 : A1;
        const float* Bt = seg ? B2 : B1;
        const int lda   = seg ? lda2 : lda1;
        const int ldb   = seg ? ldb2 : ldb1;
        const int K     = seg ? K2 : K1;
        if (K == 0) break;
        const int nk = K / GBK;

        #pragma unroll
        for (int s = 0; s < 3; s++) {
            const uint32_t sb = sbase + s * STAGE_B;
            const int k0 = s * GBK;
            #pragma unroll
            for (int i = 0; i < 4; i++) {
                cp_async16(sb + offA[i], &A[(size_t)(brow + arow[i]) * lda + k0 + achk[i]]);
                cp_async16(sb + offB[i], &Bt[(size_t)(bcol + arow[i]) * ldb + k0 + achk[i]]);
            }
            CP_COMMIT();
        }

        for (int kt = 0; kt < nk; kt++) {
            CP_WAIT2();
            __syncthreads();
            if (kt + 3 < nk) {
                const uint32_t sb = sbase + ((kt + 3) & 3) * STAGE_B;
                const int k0 = (kt + 3) * GBK;
                #pragma unroll
                for (int i = 0; i < 4; i++) {
                    cp_async16(sb + offA[i], &A[(size_t)(brow + arow[i]) * lda + k0 + achk[i]]);
                    cp_async16(sb + offB[i], &Bt[(size_t)(bcol + arow[i]) * ldb + k0 + achk[i]]);
                }
            }
            CP_COMMIT();   // always commit: keeps group-count invariant

            const uint32_t* Asb = gsm + (kt & 3) * STAGE_W;
            const uint32_t* Bsb = Asb + BOFF_W;

            #pragma unroll
            for (int ks = 0; ks < 2; ks++) {
                const int kk = ks * 8;
                uint32_t af[4][4], bf[8][2];
                #pragma unroll
                for (int mi = 0; mi < 4; mi++) {
                    int r = wm + mi * 16 + g;
                    af[mi][0] = Asb[r * APADW + kk + tg];
                    af[mi][1] = Asb[(r + 8) * APADW + kk + tg];
                    af[mi][2] = Asb[r * APADW + kk + tg + 4];
                    af[mi][3] = Asb[(r + 8) * APADW + kk + tg + 4];
                }
                #pragma unroll
                for (int ni = 0; ni < 8; ni++) {
                    int c = wn + ni * 8 + g;
                    uint2 bv = *(const uint2*)&Bsb[c * BPADW + kk + 2 * tg];
                    bf[ni][0] = bv.x; bf[ni][1] = bv.y;
                }
                #pragma unroll
                for (int mi = 0; mi < 4; mi++)
                    #pragma unroll
                    for (int ni = 0; ni < 8; ni++)
                        mma_tf32(acc[mi][ni], af[mi], bf[ni]);
            }
        }
        __syncthreads();   // stage reuse across segments
    }

    #pragma unroll
    for (int mi = 0; mi < 4; mi++) {
        int r0 = brow + wm + mi * 16 + g;
        int r1 = r0 + 8;
        #pragma unroll
        for (int ni = 0; ni < 8; ni++) {
            int cc = bcol + wn + ni * 8 + tg * 2;
            float2 b2 = *(const float2*)&bias[cc];
            float v0 = acc[mi][ni][0] + b2.x;
            float v1 = acc[mi][ni][1] + b2.y;
            float v2 = acc[mi][ni][2] + b2.x;
            float v3 = acc[mi][ni][3] + b2.y;
            if (res) {
                float2 ra = *(const float2*)&res[(size_t)r0 * ldres + cc];
                float2 rb = *(const float2*)&res[(size_t)r1 * ldres + cc];
                v0 += ra.x; v1 += ra.y; v2 += rb.x; v3 += rb.y;
            }
            if (roundC) {
                v0 = roundtf(v0); v1 = roundtf(v1);
                v2 = roundtf(v2); v3 = roundtf(v3);
            }
            *(float2*)&C[(size_t)r0 * ldc + cc] = make_float2(v0, v1);
            *(float2*)&C[(size_t)r1 * ldc + cc] = make_float2(v2, v3);
        }
    }
}

// ------------------------------------------------------------ RoPE split ---
__global__ void rope_kernel(const float* __restrict__ freqs)
{
    int idx = blockIdx.x * blockDim.x + threadIdx.x;
    if (idx >= BB * NN * HH * 32) return;
    int i = idx & 31;
    int h = (idx >> 5) & 7;
    int n = (idx >> 8) & 2047;
    int b = idx >> 19;

    float f = freqs[(b * NN + n) * 32 + i];
    float c = cosf(f), s = sinf(f);

    int base = (b * NN + n) * 1536 + h * 64;
    int rowb = ((b * HH + h) * NN + n) * 32;

    float q1 = g_qkv[base + 2*i], q2 = g_qkv[base + 2*i + 1];
    g_qb[rowb + i] = pack_bf16((q1 * c - q2 * s) * 0.125f,
                               (q1 * s + q2 * c) * 0.125f);

    float k1 = g_qkv[base + 512 + 2*i], k2 = g_qkv[base + 512 + 2*i + 1];
    g_kb[rowb + PI8(i)] = pack_bf16(k1 * c - k2 * s, k1 * s + k2 * c);
}

// ----------------------------------------------- V transpose to bf16x2 -----
__global__ __launch_bounds__(128) void vtrans_kernel()
{
    __shared__ float ts[64 * 65];
    const int bh = blockIdx.x;
    const int b = bh >> 3, h = bh & 7;
    const int n0 = blockIdx.y * 64;
    const int tid = threadIdx.x;

    {
        const int r = tid >> 1, cb = (tid & 1) * 32;
        const float* src = g_qkv + (size_t)(b * NN + n0 + r) * 1536 + 1024 + h * 64 + cb;
        #pragma unroll
        for (int c = 0; c < 8; c++) {
            float4 v = *(const float4*)&src[c * 4];
            float* d = &ts[r * 65 + cb + c * 4];
            d[0] = v.x; d[1] = v.y; d[2] = v.z; d[3] = v.w;
        }
    }
    __syncthreads();

    const int wp = tid >> 5, p = tid & 31;
    const int pp = PI8(p);
    #pragma unroll
    for (int it = 0; it < 16; it++) {
        const int d = wp + it * 4;
        uint32_t word = pack_bf16(ts[(2 * p) * 65 + d], ts[(2 * p + 1) * 65 + d]);
        g_vtb[(size_t)(bh * 64 + d) * 1024 + (n0 >> 1) + pp] = word;
    }
}

// ---------------------------- bf16 flash attention (R14) -------------------
#define VSW 40
#define STG_W (64 * VSW * 2)
#define VOFF_B (64 * VSW * 4)
#define ATT_SMEM (3 * STG_W * 4)       // 61440 B

__global__ __launch_bounds__(256, 2) void attn_bf16()
{
    extern __shared__ uint32_t sm[];
    const uint32_t sbase = (uint32_t)__cvta_generic_to_shared(sm);

    const int bh = blockIdx.y;
    const int q0 = blockIdx.x * 128;
    const uint32_t* __restrict__ Qw = g_qb + (size_t)bh * NN * 32;
    const uint32_t* __restrict__ Kw = g_kb + (size_t)bh * NN * 32;
    const uint32_t* __restrict__ Vw = g_vtb + (size_t)bh * 64 * 1024;

    const int tid  = threadIdx.x;
    const int w    = tid >> 5;
    const int lane = tid & 31;
    const int g    = lane >> 2;
    const int tg   = lane & 3;
    const int w16  = w * 16;

    uint32_t qa[4][4];
    {
        const int r0 = q0 + w16 + g, r1 = r0 + 8;
        #pragma unroll
        for (int ks = 0; ks < 4; ks++) {
            qa[ks][0] = Qw[r0 * 32 + ks * 8 + tg];
            qa[ks][1] = Qw[r1 * 32 + ks * 8 + tg];
            qa[ks][2] = Qw[r0 * 32 + ks * 8 + tg + 4];
            qa[ks][3] = Qw[r1 * 32 + ks * 8 + tg + 4];
        }
    }

    const int row0 = tid >> 3;
    const int cc   = (tid & 7) * 4;
    const uint32_t dst0 = (uint32_t)(row0 * VSW + cc) * 4;
    const uint32_t dst1 = (uint32_t)((row0 + 32) * VSW + cc) * 4;

    float m0 = -1e30f, m1 = -1e30f, l0 = 0.f, l1 = 0.f;
    float oacc[8][4];
    #pragma unroll
    for (int nt = 0; nt < 8; nt++)
        #pragma unroll
        for (int q = 0; q < 4; q++) oacc[nt][q] = 0.f;

    #pragma unroll
    for (int s = 0; s < 2; s++) {
        const uint32_t sb = sbase + s * STG_W * 4;
        const int k0 = s * 64;
        cp_async16(sb + dst0, Kw + (k0 + row0) * 32 + cc);
        cp_async16(sb + dst1, Kw + (k0 + row0 + 32) * 32 + cc);
        cp_async16(sb + VOFF_B + dst0, Vw + row0 * 1024 + (k0 >> 1) + cc);
        cp_async16(sb + VOFF_B + dst1, Vw + (row0 + 32) * 1024 + (k0 >> 1) + cc);
        CP_COMMIT();
    }

    int stage = 0;
    for (int kt = 0; kt < 32; kt++) {
        CP_WAIT1();
        __syncthreads();
        if (kt + 2 < 32) {
            const int s2 = (stage + 2 >= 3) ? stage - 1 : stage + 2;
            const uint32_t sb = sbase + s2 * STG_W * 4;
            const int k0 = (kt + 2) * 64;
            cp_async16(sb + dst0, Kw + (k0 + row0) * 32 + cc);
            cp_async16(sb + dst1, Kw + (k0 + row0 + 32) * 32 + cc);
            cp_async16(sb + VOFF_B + dst0, Vw + row0 * 1024 + (k0 >> 1) + cc);
            cp_async16(sb + VOFF_B + dst1, Vw + (row0 + 32) * 1024 + (k0 >> 1) + cc);
        }
        CP_COMMIT();

        const uint32_t* Ks  = sm + stage * STG_W;
        const uint32_t* Vst = Ks + 64 * VSW;
        stage = (stage + 1 == 3) ? 0 : stage + 1;

        float sacc[8][4];
        #pragma unroll
        for (int nt = 0; nt < 8; nt++)
            #pragma unroll
            for (int q = 0; q < 4; q++) sacc[nt][q] = 0.f;

        #pragma unroll
        for (int ks = 0; ks < 4; ks++) {
            const int wb = ks * 8 + 2 * tg;
            #pragma unroll
            for (int nt = 0; nt < 8; nt++) {
                uint2 bv = *(const uint2*)&Ks[(nt * 8 + g) * VSW + wb];
                mma_bf16(sacc[nt], qa[ks], bv.x, bv.y);
            }
        }

        float mt0 = -1e30f, mt1 = -1e30f;
        #pragma unroll
        for (int nt = 0; nt < 8; nt++) {
            mt0 = fmaxf(mt0, fmaxf(sacc[nt][0], sacc[nt][1]));
            mt1 = fmaxf(mt1, fmaxf(sacc[nt][2], sacc[nt][3]));
        }
        mt0 = fmaxf(mt0, __shfl_xor_sync(0xffffffffu, mt0, 1));
        mt0 = fmaxf(mt0, __shfl_xor_sync(0xffffffffu, mt0, 2));
        mt1 = fmaxf(mt1, __shfl_xor_sync(0xffffffffu, mt1, 1));
        mt1 = fmaxf(mt1, __shfl_xor_sync(0xffffffffu, mt1, 2));
        float mn0 = fmaxf(m0, mt0), mn1 = fmaxf(m1, mt1);

        float rs0 = 0.f, rs1 = 0.f;
        #pragma unroll
        for (int nt = 0; nt < 8; nt++) {
            sacc[nt][0] = __expf(sacc[nt][0] - mn0);
            sacc[nt][1] = __expf(sacc[nt][1] - mn0);
            sacc[nt][2] = __expf(sacc[nt][2] - mn1);
            sacc[nt][3] = __expf(sacc[nt][3] - mn1);
            rs0 += sacc[nt][0] + sacc[nt][1];
            rs1 += sacc[nt][2] + sacc[nt][3];
        }
        rs0 += __shfl_xor_sync(0xffffffffu, rs0, 1);
        rs0 += __shfl_xor_sync(0xffffffffu, rs0, 2);
        rs1 += __shfl_xor_sync(0xffffffffu, rs1, 1);
        rs1 += __shfl_xor_sync(0xffffffffu, rs1, 2);

        float c0 = __expf(m0 - mn0), c1 = __expf(m1 - mn1);
        l0 = l0 * c0 + rs0;  l1 = l1 * c1 + rs1;
        m0 = mn0;            m1 = mn1;
        #pragma unroll
        for (int nt = 0; nt < 8; nt++) {
            oacc[nt][0] *= c0; oacc[nt][1] *= c0;
            oacc[nt][2] *= c1; oacc[nt][3] *= c1;
        }

        uint32_t pa[8][2];
        #pragma unroll
        for (int nt = 0; nt < 8; nt++) {
            pa[nt][0] = pack_bf16(sacc[nt][0], sacc[nt][1]);
            pa[nt][1] = pack_bf16(sacc[nt][2], sacc[nt][3]);
        }

        #pragma unroll
        for (int ks = 0; ks < 4; ks++) {
            const int wb = ks * 8 + 2 * tg;
            uint32_t a[4] = { pa[2*ks][0], pa[2*ks][1],
                              pa[2*ks+1][0], pa[2*ks+1][1] };
            #pragma unroll
            for (int nt = 0; nt < 8; nt++) {
                uint2 bv = *(const uint2*)&Vst[(nt * 8 + g) * VSW + wb];
                mma_bf16(oacc[nt], a, bv.x, bv.y);
            }
        }
    }

    const int b = bh >> 3, h = bh & 7;
    const float inv0 = 1.f / l0, inv1 = 1.f / l1;
    const int r0 = q0 + w16 + g, r1 = r0 + 8;
    #pragma unroll
    for (int nt = 0; nt < 8; nt++) {
        int d = h * 64 + nt * 8 + tg * 2;
        *(float2*)&g_attn[(size_t)(b * NN + r0) * DD + d] =
            make_float2(roundtf(oacc[nt][0] * inv0), roundtf(oacc[nt][1] * inv0));
        *(float2*)&g_attn[(size_t)(b * NN + r1) * DD + d] =
            make_float2(roundtf(oacc[nt][2] * inv1), roundtf(oacc[nt][3] * inv1));
    }
}

// ------------------------------------------------------- LayerNorm + GELU --
__global__ __launch_bounds__(256) void ln_gelu_kernel(
    const float* __restrict__ gamma, const float* __restrict__ beta)
{
    const int r = blockIdx.x;
    const int t = threadIdx.x;
    float4 v = *(const float4*)&g_h1[(size_t)r * 1024 + t * 4];

    float sum = v.x + v.y + v.z + v.w;
    float sq  = v.x*v.x + v.y*v.y + v.z*v.z + v.w*v.w;
    #pragma unroll
    for (int off = 16; off >= 1; off >>= 1) {
        sum += __shfl_xor_sync(0xffffffffu, sum, off);
        sq  += __shfl_xor_sync(0xffffffffu, sq, off);
    }
    __shared__ float ssum[8], ssq[8];
    if ((t & 31) == 0) { ssum[t >> 5] = sum; ssq[t >> 5] = sq; }
    __syncthreads();
    float tot = 0.f, totq = 0.f;
    #pragma unroll
    for (int w = 0; w < 8; w++) { tot += ssum[w]; totq += ssq[w]; }

    float mean = tot * (1.f / 1024.f);
    float var  = totq * (1.f / 1024.f) - mean * mean;
    float inv  = rsqrtf(var + 1e-5f);

    float4 g4 = *(const float4*)&gamma[t * 4];
    float4 b4 = *(const float4*)&beta[t * 4];
    float y; float4 o;
    y = (v.x - mean) * inv * g4.x + b4.x; o.x = roundtf(0.5f * y * (1.f + erff(y * 0.70710678f)));
    y = (v.y - mean) * inv * g4.y + b4.y; o.y = roundtf(0.5f * y * (1.f + erff(y * 0.70710678f)));
    y = (v.z - mean) * inv * g4.z + b4.z; o.z = roundtf(0.5f * y * (1.f + erff(y * 0.70710678f)));
    y = (v.w - mean) * inv * g4.w + b4.w; o.w = roundtf(0.5f * y * (1.f + erff(y * 0.70710678f)));
    *(float4*)&g_h1[(size_t)r * 1024 + t * 4] = o;
}

// ------------------------------------------------------------- launcher ----
extern "C" void kernel_launch(void* const* d_in, const int* in_sizes, int n_in,
                              void* d_out, int out_size)
{
    const float* x      = (const float*)d_in[0];
    const float* freqs  = (const float*)d_in[1];
    const float* wqkv_w = (const float*)d_in[2];
    const float* wqkv_b = (const float*)d_in[3];
    const float* out_w  = (const float*)d_in[4];
    const float* out_b  = (const float*)d_in[5];
    const float* ffn1_w = (const float*)d_in[6];
    const float* ffn1_b = (const float*)d_in[7];
    const float* ln_g   = (const float*)d_in[8];
    const float* ln_b   = (const float*)d_in[9];
    const float* ffn2_w = (const float*)d_in[10];
    const float* ffn2_b = (const float*)d_in[11];
    float* out = (float*)d_out;

    float *p_qkv, *p_attn, *p_hcat, *p_h1, *p_xr, *p_wr, *p_wct, *p_bias2, *p_zero;
    cudaGetSymbolAddress((void**)&p_qkv,   g_qkv);
    cudaGetSymbolAddress((void**)&p_attn,  g_attn);
    cudaGetSymbolAddress((void**)&p_hcat,  g_hcat);
    cudaGetSymbolAddress((void**)&p_h1,    g_h1);
    cudaGetSymbolAddress((void**)&p_xr,    g_xr);
    cudaGetSymbolAddress((void**)&p_wr,    g_wr);
    cudaGetSymbolAddress((void**)&p_wct,   g_wct);
    cudaGetSymbolAddress((void**)&p_bias2, g_bias2);
    cudaGetSymbolAddress((void**)&p_zero,  g_zero);

    cudaFuncSetAttribute(gemm_tf32,
                         cudaFuncAttributeMaxDynamicSharedMemorySize, GEMM_SMEM);
    cudaFuncSetAttribute(attn_bf16,
                         cudaFuncAttributeMaxDynamicSharedMemorySize, ATT_SMEM);

    // 0a. round x
    round_x<<<(MROWS*DD/4 + 255)/256, 256>>>(x);
    // 0b. weight prep
    transpose_round_pi<<<dim3(1536/32, 512/32), dim3(32,8)>>>(wqkv_w, p_wr + WOFF_QKV, 512, 1536);
    round_outw<<<(512*512/4 + 255)/256, 256>>>(out_w);
    transpose_round_pi<<<dim3(1024/32, 512/32), dim3(32,8)>>>(ffn1_w, p_wr + WOFF_FFN1, 512, 1024);
    transpose_round_pi<<<dim3(1024/32, 512/32), dim3(32,8)>>>(ffn1_w + 512*1024, p_wr + WOFF_FFN1B, 512, 1024);
    transpose_round_pi<<<dim3(512/32, 1024/32), dim3(32,8)>>>(ffn2_w, p_wr + WOFF_FFN2, 1024, 512);
    // 0c. bias2 = ffn1_b + out_b @ W1_bot
    bias2_kernel<<<4, 256>>>(ffn1_w, ffn1_b, out_b);
    // 0d. Wc = out_w @ W1_bot  ([512][1024] f32, staged in g_hcat)
    gemm_tf32<<<dim3(1024/GBN, 512/GBM), 128, GEMM_SMEM>>>(
        p_wr + WOFF_OUT, 512, p_wr + WOFF_FFN1B, 512, 512,
        nullptr, 0, nullptr, 0, 0,
        p_hcat, 1024, p_zero, nullptr, 0, 0);
    // 0e. Wc -> Wc^T [1024][512] pi-permuted rounded
    transpose_round_pi<<<dim3(1024/32, 512/32), dim3(32,8)>>>(p_hcat, p_wct, 512, 1024);

    // 1. QKV projection: [8192,512] @ [512,1536]
    gemm_tf32<<<dim3(1536/GBN, MROWS/GBM), 128, GEMM_SMEM>>>(
        p_xr, DD, p_wr + WOFF_QKV, 512, 512,
        nullptr, 0, nullptr, 0, 0,
        p_qkv, 1536, wqkv_b, nullptr, 0, 0);

    // 2. RoPE -> bf16 Q/K; V transpose -> bf16
    rope_kernel<<<(BB*NN*HH*32 + 255)/256, 256>>>(freqs);
    vtrans_kernel<<<dim3(BB*HH, NN/64), 128>>>();

    // 3. Attention (bf16 mma, cp.async ring, LDS.64 B-frags)
    attn_bf16<<<dim3(NN/128, BB*HH), 256, ATT_SMEM>>>();

    // 4. FFN1 fused with out-proj:
    //    h1 = x@W1top + attn@Wc + bias2
    gemm_tf32<<<dim3(1024/GBN, MROWS/GBM), 128, GEMM_SMEM>>>(
        p_xr, DD, p_wr + WOFF_FFN1, 512, 512,
        p_attn, DD, p_wct, 512, 512,
        p_h1, 1024, p_bias2, nullptr, 0, 0);

    // 5. LayerNorm + exact GELU (in place, stores rounded)
    ln_gelu_kernel<<<MROWS, 256>>>(ln_g, ln_b);

    // 6. FFN2 + residual: out = x + h1 @ [1024,512] + b
    gemm_tf32<<<dim3(512/GBN, MROWS/GBM), 128, GEMM_SMEM>>>(
        p_h1, 1024, p_wr + WOFF_FFN2, 1024, 1024,
        nullptr, 0, nullptr, 0, 0,
        out, DD, ffn2_b, x, DD, 0);
}